// round 2
// baseline (speedup 1.0000x reference)
#include <cuda_runtime.h>
#include <math.h>

#define D_MODEL 1024
#define NHEADS  16
#define HDIM    64
#define BATCH   4
#define SEQ     2048
#define MROWS   (BATCH*SEQ)   // 8192

// Scratch (device globals — no allocations allowed)
__device__ float g_Q[(size_t)MROWS * D_MODEL];
__device__ float g_K[(size_t)MROWS * D_MODEL];
__device__ float g_V[(size_t)MROWS * D_MODEL];
__device__ float g_C[(size_t)MROWS * D_MODEL];

// ---------------------------------------------------------------------------
// SGEMM: C[M,N] = A[M,K] @ W[K,N] + bias[N]
// M=8192, N=K=1024. BM=BN=128, BK=16, 256 threads, 8x8 microtile.
// REMAP=1: write output head-split as [B, H, S, HDIM].
// ---------------------------------------------------------------------------
template<int REMAP>
__global__ __launch_bounds__(256)
void gemm_bias(const float* __restrict__ A, const float* __restrict__ W,
               const float* __restrict__ bias, float* __restrict__ C)
{
    const int N = D_MODEL, K = D_MODEL;
    const int BM = 128, BN = 128, BK = 16;

    __shared__ float As[BK][BM + 4];   // transposed A tile
    __shared__ float Bs[BK][BN + 4];

    const int t  = threadIdx.x;
    const int tx = t & 15;
    const int ty = t >> 4;
    const int m0 = blockIdx.y * BM;
    const int n0 = blockIdx.x * BN;

    float acc[8][8];
    #pragma unroll
    for (int i = 0; i < 8; i++)
        #pragma unroll
        for (int j = 0; j < 8; j++) acc[i][j] = 0.f;

    const int arow = t >> 2;         // 0..63
    const int acol = (t & 3) * 4;    // 0,4,8,12
    const int brow = t >> 5;         // 0..7
    const int bcol = (t & 31) * 4;   // 0..124

    for (int k0 = 0; k0 < K; k0 += BK) {
        #pragma unroll
        for (int r = 0; r < 2; r++) {
            int row = arow + r * 64;
            float4 v = *(const float4*)&A[(size_t)(m0 + row) * K + k0 + acol];
            As[acol + 0][row] = v.x;
            As[acol + 1][row] = v.y;
            As[acol + 2][row] = v.z;
            As[acol + 3][row] = v.w;
        }
        #pragma unroll
        for (int r = 0; r < 2; r++) {
            int row = brow + r * 8;
            float4 v = *(const float4*)&W[(size_t)(k0 + row) * N + n0 + bcol];
            *(float4*)&Bs[row][bcol] = v;
        }
        __syncthreads();

        #pragma unroll
        for (int kk = 0; kk < BK; kk++) {
            float ra[8], rb[8];
            *(float4*)&ra[0] = *(float4*)&As[kk][ty * 8];
            *(float4*)&ra[4] = *(float4*)&As[kk][ty * 8 + 4];
            *(float4*)&rb[0] = *(float4*)&Bs[kk][tx * 8];
            *(float4*)&rb[4] = *(float4*)&Bs[kk][tx * 8 + 4];
            #pragma unroll
            for (int i = 0; i < 8; i++)
                #pragma unroll
                for (int j = 0; j < 8; j++)
                    acc[i][j] += ra[i] * rb[j];
        }
        __syncthreads();
    }

    #pragma unroll
    for (int i = 0; i < 8; i++) {
        int m = m0 + ty * 8 + i;
        #pragma unroll
        for (int j = 0; j < 8; j++) {
            int n = n0 + tx * 8 + j;
            float v = acc[i][j] + bias[n];
            if (REMAP) {
                int b = m >> 11, s = m & 2047, h = n >> 6, d = n & 63;
                C[((((size_t)b * NHEADS + h) * SEQ + s) << 6) + d] = v;
            } else {
                C[(size_t)m * N + n] = v;
            }
        }
    }
}

// ---------------------------------------------------------------------------
// Causal flash attention, fp32.
// Q/K/V in [B*H, S, HDIM]. Output ctx in [B, S, D_MODEL].
// Block = 256 threads handles one 64-query tile of one (b,h).
// ---------------------------------------------------------------------------
#define SPAD 68   // 64 + 4, keeps float4 alignment (div by 4)

__global__ __launch_bounds__(256)
void flash_attn(const float* __restrict__ Q, const float* __restrict__ K,
                const float* __restrict__ V, float* __restrict__ ctx)
{
    extern __shared__ float sm[];
    float* Qt   = sm;                 // [64][SPAD]  Qt[d][q]
    float* Kt   = Qt + 64 * SPAD;     // Kt[d][k]
    float* Vs   = Kt + 64 * SPAD;     // Vs[k][d]
    float* Pt   = Vs + 64 * SPAD;     // Pt[k][q]
    float* mrow = Pt + 64 * SPAD;     // [64]
    float* lrow = mrow + 64;          // [64]
    float* arow = lrow + 64;          // [64] alpha

    const int t  = threadIdx.x;
    const int tx = t & 15;
    const int ty = t >> 4;
    const int qt = blockIdx.x;        // 0..31
    const int bh = blockIdx.y;        // 0..63
    const int q0 = qt * 64;
    const float scale = 0.125f;       // 1/sqrt(64)

    // Load Q tile transposed
    {
        const float* Qb = Q + ((size_t)bh * SEQ + q0) * HDIM;
        int r  = t >> 2;
        int dv = (t & 3) * 16;
        #pragma unroll
        for (int i = 0; i < 4; i++) {
            float4 v = *(const float4*)&Qb[r * HDIM + dv + i * 4];
            Qt[(dv + i * 4 + 0) * SPAD + r] = v.x;
            Qt[(dv + i * 4 + 1) * SPAD + r] = v.y;
            Qt[(dv + i * 4 + 2) * SPAD + r] = v.z;
            Qt[(dv + i * 4 + 3) * SPAD + r] = v.w;
        }
    }
    if (t < 64) { mrow[t] = -INFINITY; lrow[t] = 0.f; }

    float o[4][4];
    #pragma unroll
    for (int i = 0; i < 4; i++)
        #pragma unroll
        for (int j = 0; j < 4; j++) o[i][j] = 0.f;

    const int r0 = ty * 4;  // query rows
    const int c0 = tx * 4;  // key cols (S) / head dims (PV)

    for (int kt = 0; kt <= qt; kt++) {
        int k0 = kt * 64;
        const float* Kb = K + ((size_t)bh * SEQ + k0) * HDIM;
        const float* Vb = V + ((size_t)bh * SEQ + k0) * HDIM;

        __syncthreads();  // prior iteration done reading Kt/Vs/Pt

        // Load K (transposed) and V (row-major)
        {
            int r  = t >> 2;
            int dv = (t & 3) * 16;
            #pragma unroll
            for (int i = 0; i < 4; i++) {
                float4 v = *(const float4*)&Kb[r * HDIM + dv + i * 4];
                Kt[(dv + i * 4 + 0) * SPAD + r] = v.x;
                Kt[(dv + i * 4 + 1) * SPAD + r] = v.y;
                Kt[(dv + i * 4 + 2) * SPAD + r] = v.z;
                Kt[(dv + i * 4 + 3) * SPAD + r] = v.w;
                float4 w = *(const float4*)&Vb[r * HDIM + dv + i * 4];
                *(float4*)&Vs[r * SPAD + dv + i * 4] = w;
            }
        }
        __syncthreads();

        // S = (Q K^T) * scale, causal mask
        float s[4][4];
        #pragma unroll
        for (int i = 0; i < 4; i++)
            #pragma unroll
            for (int j = 0; j < 4; j++) s[i][j] = 0.f;

        #pragma unroll 8
        for (int d = 0; d < 64; d++) {
            float4 qv = *(float4*)&Qt[d * SPAD + r0];
            float4 kv = *(float4*)&Kt[d * SPAD + c0];
            float qa[4] = {qv.x, qv.y, qv.z, qv.w};
            float ka[4] = {kv.x, kv.y, kv.z, kv.w};
            #pragma unroll
            for (int i = 0; i < 4; i++)
                #pragma unroll
                for (int j = 0; j < 4; j++)
                    s[i][j] += qa[i] * ka[j];
        }
        #pragma unroll
        for (int i = 0; i < 4; i++)
            #pragma unroll
            for (int j = 0; j < 4; j++) {
                float val = s[i][j] * scale;
                if (k0 + c0 + j > q0 + r0 + i) val = -INFINITY;
                s[i][j] = val;
                Pt[(c0 + j) * SPAD + (r0 + i)] = val;  // raw, for row max
            }
        __syncthreads();

        // Per-row max + alpha (threads 0..63, one row each)
        if (t < 64) {
            float mold = mrow[t];
            float mx = mold;
            #pragma unroll 8
            for (int k = 0; k < 64; k++) mx = fmaxf(mx, Pt[k * SPAD + t]);
            float al = (mold == -INFINITY) ? 0.f : __expf(mold - mx);
            mrow[t] = mx;
            arow[t] = al;
        }
        __syncthreads();

        // Exponentiate (from registers) + rescale O accumulator
        #pragma unroll
        for (int i = 0; i < 4; i++) {
            float mnew = mrow[r0 + i];
            float al   = arow[r0 + i];
            #pragma unroll
            for (int j = 0; j < 4; j++) {
                float p = (s[i][j] == -INFINITY) ? 0.f : __expf(s[i][j] - mnew);
                Pt[(c0 + j) * SPAD + (r0 + i)] = p;
                o[i][j] *= al;
            }
        }
        __syncthreads();

        // Row sums (threads 0..63)
        if (t < 64) {
            float sum = 0.f;
            #pragma unroll 8
            for (int k = 0; k < 64; k++) sum += Pt[k * SPAD + t];
            lrow[t] = lrow[t] * arow[t] + sum;
        }

        // O += P @ V
        #pragma unroll 8
        for (int k = 0; k < 64; k++) {
            float4 pv = *(float4*)&Pt[k * SPAD + r0];
            float4 vv = *(float4*)&Vs[k * SPAD + c0];
            float pa[4] = {pv.x, pv.y, pv.z, pv.w};
            float va[4] = {vv.x, vv.y, vv.z, vv.w};
            #pragma unroll
            for (int i = 0; i < 4; i++)
                #pragma unroll
                for (int j = 0; j < 4; j++)
                    o[i][j] += pa[i] * va[j];
        }
    }
    __syncthreads();

    // Write ctx in [B, S, D_MODEL]
    const int b = bh >> 4;
    const int h = bh & 15;
    #pragma unroll
    for (int i = 0; i < 4; i++) {
        int q = q0 + r0 + i;
        float inv_l = 1.f / lrow[r0 + i];
        #pragma unroll
        for (int j = 0; j < 4; j++) {
            ctx[((size_t)b * SEQ + q) * D_MODEL + h * HDIM + c0 + j] = o[i][j] * inv_l;
        }
    }
}

// ---------------------------------------------------------------------------
extern "C" void kernel_launch(void* const* d_in, const int* in_sizes, int n_in,
                              void* d_out, int out_size)
{
    const float* in_q = (const float*)d_in[0];
    const float* in_k = (const float*)d_in[1];
    const float* in_v = (const float*)d_in[2];
    const float* Wq   = (const float*)d_in[3];
    const float* bq   = (const float*)d_in[4];
    const float* Wk   = (const float*)d_in[5];
    const float* bk   = (const float*)d_in[6];
    const float* Wv   = (const float*)d_in[7];
    const float* bv   = (const float*)d_in[8];
    const float* Wo   = (const float*)d_in[9];
    const float* bo   = (const float*)d_in[10];
    float* out = (float*)d_out;

    float *gq, *gk, *gv, *gc;
    cudaGetSymbolAddress((void**)&gq, g_Q);
    cudaGetSymbolAddress((void**)&gk, g_K);
    cudaGetSymbolAddress((void**)&gv, g_V);
    cudaGetSymbolAddress((void**)&gc, g_C);

    const int smem_attn = (4 * 64 * SPAD + 3 * 64) * (int)sizeof(float);
    cudaFuncSetAttribute(flash_attn, cudaFuncAttributeMaxDynamicSharedMemorySize, smem_attn);

    dim3 gemm_grid(D_MODEL / 128, MROWS / 128);  // (8, 64)
    gemm_bias<1><<<gemm_grid, 256>>>(in_q, Wq, bq, gq);
    gemm_bias<1><<<gemm_grid, 256>>>(in_k, Wk, bk, gk);
    gemm_bias<1><<<gemm_grid, 256>>>(in_v, Wv, bv, gv);

    dim3 attn_grid(SEQ / 64, BATCH * NHEADS);    // (32, 64)
    flash_attn<<<attn_grid, 256, smem_attn>>>(gq, gk, gv, gc);

    gemm_bias<0><<<gemm_grid, 256>>>(gc, Wo, bo, out);
}

// round 4
// speedup vs baseline: 2.0879x; 2.0879x over previous
#include <cuda_runtime.h>
#include <math.h>
#include <stdint.h>

#define D_MODEL 1024
#define NHEADS  16
#define HDIM    64
#define BATCH   4
#define SEQ     2048
#define MROWS   (BATCH*SEQ)   // 8192

// Scratch (device globals — no allocations allowed)
__device__ float g_Q[(size_t)MROWS * D_MODEL];
__device__ float g_K[(size_t)MROWS * D_MODEL];
__device__ float g_V[(size_t)MROWS * D_MODEL];
__device__ float g_C[(size_t)MROWS * D_MODEL];

__device__ __forceinline__ float to_tf32(float x) {
    asm("cvt.rna.tf32.f32 %0, %0;" : "+f"(x));
    return x;
}

__device__ __forceinline__ void mma_tf32(float c[4], const uint32_t a[4], const uint32_t b[2]) {
    asm volatile(
        "mma.sync.aligned.m16n8k8.row.col.f32.tf32.tf32.f32 "
        "{%0,%1,%2,%3},{%4,%5,%6,%7},{%8,%9},{%0,%1,%2,%3};"
        : "+f"(c[0]), "+f"(c[1]), "+f"(c[2]), "+f"(c[3])
        : "r"(a[0]), "r"(a[1]), "r"(a[2]), "r"(a[3]), "r"(b[0]), "r"(b[1]));
}

// ---------------------------------------------------------------------------
// tf32 tensor-core GEMM: C[M,N] = A[M,K] @ W[K,N] + bias[N]
// M=8192, N=K=1024. BM=BN=128, BK=32, 256 threads (8 warps, 64x32 warp tiles).
// REMAP=1: write output head-split as [B, H, S, HDIM].
// ---------------------------------------------------------------------------
template<int REMAP>
__global__ __launch_bounds__(256, 2)
void gemm_tf32(const float* __restrict__ A, const float* __restrict__ W,
               const float* __restrict__ bias, float* __restrict__ C)
{
    const int K = D_MODEL, N = D_MODEL;
    const int BM = 128, BN = 128, BK = 32;

    __shared__ float As[BM][BK + 4];   // [m][k] — conflict-free A-frag loads
    __shared__ float Bs[BK][BN + 4];   // [k][n] — conflict-free stores, 2-way frag loads

    const int t    = threadIdx.x;
    const int lane = t & 31;
    const int warp = t >> 5;
    const int g    = lane >> 2;   // groupID (row within fragment)
    const int tg   = lane & 3;    // thread-in-group (k / col pair)
    const int wm   = (warp & 1) * 64;
    const int wn   = (warp >> 1) * 32;
    const int m0   = blockIdx.y * BM;
    const int n0   = blockIdx.x * BN;

    float acc[4][4][4];
    #pragma unroll
    for (int mt = 0; mt < 4; mt++)
        #pragma unroll
        for (int nt = 0; nt < 4; nt++)
            #pragma unroll
            for (int i = 0; i < 4; i++) acc[mt][nt][i] = 0.f;

    for (int k0 = 0; k0 < K; k0 += BK) {
        // Load A tile (128x32): 4 passes, float4 along k
        #pragma unroll
        for (int p = 0; p < 4; p++) {
            int r  = (t >> 3) + p * 32;
            int c4 = (t & 7) * 4;
            float4 v = *(const float4*)&A[(size_t)(m0 + r) * K + k0 + c4];
            float4 w;
            w.x = to_tf32(v.x); w.y = to_tf32(v.y);
            w.z = to_tf32(v.z); w.w = to_tf32(v.w);
            *(float4*)&As[r][c4] = w;
        }
        // Load B tile (32x128): 4 passes, float4 along n
        #pragma unroll
        for (int p = 0; p < 4; p++) {
            int r  = (t >> 5) + p * 8;
            int c4 = (t & 31) * 4;
            float4 v = *(const float4*)&W[(size_t)(k0 + r) * N + n0 + c4];
            float4 w;
            w.x = to_tf32(v.x); w.y = to_tf32(v.y);
            w.z = to_tf32(v.z); w.w = to_tf32(v.w);
            *(float4*)&Bs[r][c4] = w;
        }
        __syncthreads();

        #pragma unroll
        for (int ks = 0; ks < 4; ks++) {
            uint32_t a[4][4], b[4][2];
            const int kk = ks * 8 + tg;
            #pragma unroll
            for (int mt = 0; mt < 4; mt++) {
                int m = wm + mt * 16 + g;
                a[mt][0] = *(const uint32_t*)&As[m][kk];
                a[mt][1] = *(const uint32_t*)&As[m + 8][kk];
                a[mt][2] = *(const uint32_t*)&As[m][kk + 4];
                a[mt][3] = *(const uint32_t*)&As[m + 8][kk + 4];
            }
            #pragma unroll
            for (int nt = 0; nt < 4; nt++) {
                int n = wn + nt * 8 + g;
                b[nt][0] = *(const uint32_t*)&Bs[kk][n];
                b[nt][1] = *(const uint32_t*)&Bs[kk + 4][n];
            }
            #pragma unroll
            for (int mt = 0; mt < 4; mt++)
                #pragma unroll
                for (int nt = 0; nt < 4; nt++)
                    mma_tf32(acc[mt][nt], a[mt], b[nt]);
        }
        __syncthreads();
    }

    // Epilogue: bias + store (float2 per fragment row)
    #pragma unroll
    for (int mt = 0; mt < 4; mt++) {
        #pragma unroll
        for (int nt = 0; nt < 4; nt++) {
            int n  = n0 + wn + nt * 8 + 2 * tg;
            float b0v = bias[n], b1v = bias[n + 1];
            #pragma unroll
            for (int half = 0; half < 2; half++) {
                int m = m0 + wm + mt * 16 + g + half * 8;
                float2 v;
                v.x = acc[mt][nt][half * 2 + 0] + b0v;
                v.y = acc[mt][nt][half * 2 + 1] + b1v;
                if (REMAP) {
                    int bb = m >> 11, s = m & 2047, h = n >> 6, d = n & 63;
                    *(float2*)&C[((((size_t)bb * NHEADS + h) * SEQ + s) << 6) + d] = v;
                } else {
                    *(float2*)&C[(size_t)m * N + n] = v;
                }
            }
        }
    }
}

// ---------------------------------------------------------------------------
// Causal flash attention, tf32 tensor cores.
// Q/K/V in [B*H, S, HDIM]. Output ctx in [B, S, D_MODEL].
// CTA = 256 threads (8 warps), 64-query x 64-key tiles.
// S mma: warps 2(m) x 4(n) -> warp tile 32q x 16k.
// PV mma: same split -> warp tile 32q x 16d (same q rows per warp).
// ---------------------------------------------------------------------------
#define ATT_LD 68   // 64 + 4 pad

__global__ __launch_bounds__(256, 2)
void flash_tf32(const float* __restrict__ Q, const float* __restrict__ K,
                const float* __restrict__ V, float* __restrict__ ctx)
{
    extern __shared__ float sm[];
    float* Qs   = sm;                      // [64][68]
    float* Ks   = sm + 64 * ATT_LD;        // [64][68]
    float* Vs   = sm + 2 * 64 * ATT_LD;    // [64][68]
    float* Ps   = sm + 3 * 64 * ATT_LD;    // [64][68]
    float* mrow = sm + 4 * 64 * ATT_LD;    // [64]
    float* lrow = mrow + 64;               // [64]
    float* arow = lrow + 64;               // [64]
    float* red  = arow + 64;               // [4][64]

    const int t    = threadIdx.x;
    const int lane = t & 31;
    const int warp = t >> 5;
    const int g    = lane >> 2;
    const int tg   = lane & 3;
    const int wq   = (warp & 1) * 32;      // q-range of this warp (both mmas)
    const int wk   = (warp >> 1) * 16;     // k-cols (S) / d-cols (PV)
    const int qt   = blockIdx.x;
    const int bh   = blockIdx.y;
    const int q0   = qt * 64;
    const float scale = 0.125f;            // 1/sqrt(64), folded into Q

    // Load Q tile, scaled + tf32
    {
        const float* Qb = Q + ((size_t)bh * SEQ + q0) * HDIM;
        #pragma unroll
        for (int p = 0; p < 4; p++) {
            int r  = (t >> 4) + p * 16;
            int c4 = (t & 15) * 4;
            float4 v = *(const float4*)&Qb[r * HDIM + c4];
            float4 w;
            w.x = to_tf32(v.x * scale); w.y = to_tf32(v.y * scale);
            w.z = to_tf32(v.z * scale); w.w = to_tf32(v.w * scale);
            *(float4*)&Qs[r * ATT_LD + c4] = w;
        }
    }
    if (t < 64) { mrow[t] = -INFINITY; lrow[t] = 0.f; }

    float o[2][2][4];
    #pragma unroll
    for (int mt = 0; mt < 2; mt++)
        #pragma unroll
        for (int nt = 0; nt < 2; nt++)
            #pragma unroll
            for (int i = 0; i < 4; i++) o[mt][nt][i] = 0.f;

    for (int kt = 0; kt <= qt; kt++) {
        const int k0 = kt * 64;
        const float* Kb = K + ((size_t)bh * SEQ + k0) * HDIM;
        const float* Vb = V + ((size_t)bh * SEQ + k0) * HDIM;

        __syncthreads();  // prior iter done with Ks/Vs/Ps/red

        #pragma unroll
        for (int p = 0; p < 4; p++) {
            int r  = (t >> 4) + p * 16;
            int c4 = (t & 15) * 4;
            float4 v = *(const float4*)&Kb[r * HDIM + c4];
            float4 w;
            w.x = to_tf32(v.x); w.y = to_tf32(v.y);
            w.z = to_tf32(v.z); w.w = to_tf32(v.w);
            *(float4*)&Ks[r * ATT_LD + c4] = w;
            float4 u = *(const float4*)&Vb[r * HDIM + c4];
            float4 x;
            x.x = to_tf32(u.x); x.y = to_tf32(u.y);
            x.z = to_tf32(u.z); x.w = to_tf32(u.w);
            *(float4*)&Vs[r * ATT_LD + c4] = x;
        }
        __syncthreads();

        // ---- S = Q K^T (scale already in Q) ----
        float sc[2][2][4];
        #pragma unroll
        for (int mt = 0; mt < 2; mt++)
            #pragma unroll
            for (int nt = 0; nt < 2; nt++)
                #pragma unroll
                for (int i = 0; i < 4; i++) sc[mt][nt][i] = 0.f;

        #pragma unroll
        for (int ks = 0; ks < 8; ks++) {
            const int kk = ks * 8 + tg;
            uint32_t a[2][4], b[2][2];
            #pragma unroll
            for (int mt = 0; mt < 2; mt++) {
                int r = wq + mt * 16 + g;
                a[mt][0] = *(const uint32_t*)&Qs[r * ATT_LD + kk];
                a[mt][1] = *(const uint32_t*)&Qs[(r + 8) * ATT_LD + kk];
                a[mt][2] = *(const uint32_t*)&Qs[r * ATT_LD + kk + 4];
                a[mt][3] = *(const uint32_t*)&Qs[(r + 8) * ATT_LD + kk + 4];
            }
            #pragma unroll
            for (int nt = 0; nt < 2; nt++) {
                int n = wk + nt * 8 + g;
                b[nt][0] = *(const uint32_t*)&Ks[n * ATT_LD + kk];
                b[nt][1] = *(const uint32_t*)&Ks[n * ATT_LD + kk + 4];
            }
            #pragma unroll
            for (int mt = 0; mt < 2; mt++)
                #pragma unroll
                for (int nt = 0; nt < 2; nt++)
                    mma_tf32(sc[mt][nt], a[mt], b[nt]);
        }

        // Store masked scores to Ps
        #pragma unroll
        for (int mt = 0; mt < 2; mt++) {
            #pragma unroll
            for (int nt = 0; nt < 2; nt++) {
                int c  = wk + nt * 8 + 2 * tg;
                int gc = k0 + c;
                #pragma unroll
                for (int half = 0; half < 2; half++) {
                    int r  = wq + mt * 16 + g + half * 8;
                    int gr = q0 + r;
                    float2 v;
                    v.x = (gc     > gr) ? -INFINITY : sc[mt][nt][half * 2 + 0];
                    v.y = (gc + 1 > gr) ? -INFINITY : sc[mt][nt][half * 2 + 1];
                    *(float2*)&Ps[r * ATT_LD + c] = v;
                }
            }
        }
        __syncthreads();

        // ---- row max partials (4 threads per row) ----
        {
            int row = t & 63, qq = t >> 6;
            const float* p = &Ps[row * ATT_LD + qq * 16];
            float mx = -INFINITY;
            #pragma unroll
            for (int j = 0; j < 4; j++) {
                float4 v = *(const float4*)&p[j * 4];
                mx = fmaxf(mx, fmaxf(fmaxf(v.x, v.y), fmaxf(v.z, v.w)));
            }
            red[qq * 64 + row] = mx;
        }
        __syncthreads();
        if (t < 64) {
            float mo = mrow[t];
            float mn = fmaxf(fmaxf(red[t], red[64 + t]),
                             fmaxf(red[128 + t], red[192 + t]));
            mn = fmaxf(mn, mo);
            mrow[t] = mn;
            arow[t] = __expf(mo - mn);   // exp(-inf)=0 on first tile
        }
        __syncthreads();

        // ---- exp + row-sum partials; rescale O accumulators ----
        {
            int row = t & 63, qq = t >> 6;
            float m = mrow[row];
            float* p = &Ps[row * ATT_LD + qq * 16];
            float sum = 0.f;
            #pragma unroll
            for (int j = 0; j < 4; j++) {
                float4 v = *(float4*)&p[j * 4];
                v.x = to_tf32(__expf(v.x - m));
                v.y = to_tf32(__expf(v.y - m));
                v.z = to_tf32(__expf(v.z - m));
                v.w = to_tf32(__expf(v.w - m));
                sum += v.x + v.y + v.z + v.w;
                *(float4*)&p[j * 4] = v;
            }
            red[qq * 64 + row] = sum;
        }
        #pragma unroll
        for (int mt = 0; mt < 2; mt++) {
            float a0 = arow[wq + mt * 16 + g];
            float a1 = arow[wq + mt * 16 + g + 8];
            #pragma unroll
            for (int nt = 0; nt < 2; nt++) {
                o[mt][nt][0] *= a0; o[mt][nt][1] *= a0;
                o[mt][nt][2] *= a1; o[mt][nt][3] *= a1;
            }
        }
        __syncthreads();
        if (t < 64) {
            lrow[t] = lrow[t] * arow[t] +
                      red[t] + red[64 + t] + red[128 + t] + red[192 + t];
        }

        // ---- O += P V ----
        #pragma unroll
        for (int ks = 0; ks < 8; ks++) {
            const int kk = ks * 8 + tg;
            uint32_t a[2][4], b[2][2];
            #pragma unroll
            for (int mt = 0; mt < 2; mt++) {
                int r = wq + mt * 16 + g;
                a[mt][0] = *(const uint32_t*)&Ps[r * ATT_LD + kk];
                a[mt][1] = *(const uint32_t*)&Ps[(r + 8) * ATT_LD + kk];
                a[mt][2] = *(const uint32_t*)&Ps[r * ATT_LD + kk + 4];
                a[mt][3] = *(const uint32_t*)&Ps[(r + 8) * ATT_LD + kk + 4];
            }
            #pragma unroll
            for (int nt = 0; nt < 2; nt++) {
                int n = wk + nt * 8 + g;
                b[nt][0] = *(const uint32_t*)&Vs[kk * ATT_LD + n];
                b[nt][1] = *(const uint32_t*)&Vs[(kk + 4) * ATT_LD + n];
            }
            #pragma unroll
            for (int mt = 0; mt < 2; mt++)
                #pragma unroll
                for (int nt = 0; nt < 2; nt++)
                    mma_tf32(o[mt][nt], a[mt], b[nt]);
        }
    }
    __syncthreads();

    // Epilogue: normalize + write ctx [B, S, D_MODEL]
    const int bb = bh >> 4;
    const int h  = bh & 15;
    #pragma unroll
    for (int mt = 0; mt < 2; mt++) {
        #pragma unroll
        for (int half = 0; half < 2; half++) {
            int r = wq + mt * 16 + g + half * 8;
            int q = q0 + r;
            float il = 1.f / lrow[r];
            #pragma unroll
            for (int nt = 0; nt < 2; nt++) {
                int d = wk + nt * 8 + 2 * tg;
                float2 v;
                v.x = o[mt][nt][half * 2 + 0] * il;
                v.y = o[mt][nt][half * 2 + 1] * il;
                *(float2*)&ctx[((size_t)bb * SEQ + q) * D_MODEL + h * HDIM + d] = v;
            }
        }
    }
}

// ---------------------------------------------------------------------------
extern "C" void kernel_launch(void* const* d_in, const int* in_sizes, int n_in,
                              void* d_out, int out_size)
{
    const float* in_q = (const float*)d_in[0];
    const float* in_k = (const float*)d_in[1];
    const float* in_v = (const float*)d_in[2];
    const float* Wq   = (const float*)d_in[3];
    const float* bq   = (const float*)d_in[4];
    const float* Wk   = (const float*)d_in[5];
    const float* bk   = (const float*)d_in[6];
    const float* Wv   = (const float*)d_in[7];
    const float* bv   = (const float*)d_in[8];
    const float* Wo   = (const float*)d_in[9];
    const float* bo   = (const float*)d_in[10];
    float* out = (float*)d_out;

    float *gq, *gk, *gv, *gc;
    cudaGetSymbolAddress((void**)&gq, g_Q);
    cudaGetSymbolAddress((void**)&gk, g_K);
    cudaGetSymbolAddress((void**)&gv, g_V);
    cudaGetSymbolAddress((void**)&gc, g_C);

    const int smem_attn = (4 * 64 * ATT_LD + 3 * 64 + 4 * 64) * (int)sizeof(float);
    static int attr_set = 0;
    if (!attr_set) {
        cudaFuncSetAttribute(flash_tf32, cudaFuncAttributeMaxDynamicSharedMemorySize, smem_attn);
        attr_set = 1;
    }

    dim3 gemm_grid(D_MODEL / 128, MROWS / 128);  // (8, 64)
    gemm_tf32<1><<<gemm_grid, 256>>>(in_q, Wq, bq, gq);
    gemm_tf32<1><<<gemm_grid, 256>>>(in_k, Wk, bk, gk);
    gemm_tf32<1><<<gemm_grid, 256>>>(in_v, Wv, bv, gv);

    dim3 attn_grid(SEQ / 64, BATCH * NHEADS);    // (32, 64)
    flash_tf32<<<attn_grid, 256, smem_attn>>>(gq, gk, gv, gc);

    gemm_tf32<0><<<gemm_grid, 256>>>(gc, Wo, bo, out);
}

// round 6
// speedup vs baseline: 3.6738x; 1.7595x over previous
#include <cuda_runtime.h>
#include <math.h>
#include <stdint.h>

#define D_MODEL 1024
#define NHEADS  16
#define HDIM    64
#define BATCH   4
#define SEQ     2048
#define MROWS   (BATCH*SEQ)   // 8192

// Scratch (device globals — no allocations allowed)
__device__ float g_Q[(size_t)MROWS * D_MODEL];
__device__ float g_K[(size_t)MROWS * D_MODEL];
__device__ float g_V[(size_t)MROWS * D_MODEL];
__device__ float g_C[(size_t)MROWS * D_MODEL];
// tf32-prerounded copies of inputs
__device__ float g_Aq[(size_t)MROWS * D_MODEL];
__device__ float g_Ak[(size_t)MROWS * D_MODEL];
__device__ float g_Av[(size_t)MROWS * D_MODEL];
__device__ float g_Wq[(size_t)D_MODEL * D_MODEL];
__device__ float g_Wk[(size_t)D_MODEL * D_MODEL];
__device__ float g_Wv[(size_t)D_MODEL * D_MODEL];
__device__ float g_Wo[(size_t)D_MODEL * D_MODEL];

__device__ __forceinline__ float to_tf32(float x) {
    asm("cvt.rna.tf32.f32 %0, %0;" : "+f"(x));
    return x;
}

__device__ __forceinline__ void mma_tf32(float c[4], const uint32_t a[4], const uint32_t b[2]) {
    asm volatile(
        "mma.sync.aligned.m16n8k8.row.col.f32.tf32.tf32.f32 "
        "{%0,%1,%2,%3},{%4,%5,%6,%7},{%8,%9},{%0,%1,%2,%3};"
        : "+f"(c[0]), "+f"(c[1]), "+f"(c[2]), "+f"(c[3])
        : "r"(a[0]), "r"(a[1]), "r"(a[2]), "r"(a[3]), "r"(b[0]), "r"(b[1]));
}

__device__ __forceinline__ void cp_async16(void* sptr, const void* gptr) {
    uint32_t s = (uint32_t)__cvta_generic_to_shared(sptr);
    asm volatile("cp.async.cg.shared.global [%0], [%1], 16;" :: "r"(s), "l"(gptr));
}
__device__ __forceinline__ void cp_commit() { asm volatile("cp.async.commit_group;"); }
template<int N> __device__ __forceinline__ void cp_wait() {
    asm volatile("cp.async.wait_group %0;" :: "n"(N));
}

// ---------------------------------------------------------------------------
// Prepass: elementwise tf32 rounding (bit-exact move of the cvt.rna that used
// to happen at smem-store time inside the GEMMs).
// ---------------------------------------------------------------------------
__global__ void cvt_tf32_kernel(const float4* __restrict__ in, float4* __restrict__ out, int n4)
{
    int i = blockIdx.x * blockDim.x + threadIdx.x;
    if (i < n4) {
        float4 v = in[i];
        v.x = to_tf32(v.x); v.y = to_tf32(v.y);
        v.z = to_tf32(v.z); v.w = to_tf32(v.w);
        out[i] = v;
    }
}

// ---------------------------------------------------------------------------
// tf32 tensor-core GEMM with 2-stage cp.async pipeline.
// C[M,N] = A[M,K] @ W[K,N] + bias. Inputs pre-rounded to tf32.
// BM=BN=128, BK=32, 256 threads (8 warps, 64x32 warp tiles).
// REMAP=1: store head-split [B,H,S,HDIM], tf32-rounded.
// ---------------------------------------------------------------------------
#define GEMM_SMEM ((2*128*36 + 2*32*132) * 4)

template<int REMAP>
__global__ __launch_bounds__(256, 2)
void gemm_tf32(const float* __restrict__ A, const float* __restrict__ W,
               const float* __restrict__ bias, float* __restrict__ C)
{
    const int K = D_MODEL, N = D_MODEL;
    extern __shared__ float smem[];
    float* As = smem;                 // [2][128][36]
    float* Bs = smem + 2 * 128 * 36;  // [2][32][132]

    const int t    = threadIdx.x;
    const int lane = t & 31;
    const int warp = t >> 5;
    const int g    = lane >> 2;
    const int tg   = lane & 3;
    const int wm   = (warp & 1) * 64;
    const int wn   = (warp >> 1) * 32;
    const int m0   = blockIdx.y * 128;
    const int n0   = blockIdx.x * 128;

    const int ar = t >> 3, ac = (t & 7) * 4;
    const int br = t >> 5, bc = (t & 31) * 4;

    float acc[4][4][4] = {};

    // Prologue: stage 0
    #pragma unroll
    for (int p = 0; p < 4; p++)
        cp_async16(&As[(ar + 32*p)*36 + ac], &A[(size_t)(m0 + ar + 32*p)*K + ac]);
    #pragma unroll
    for (int p = 0; p < 4; p++)
        cp_async16(&Bs[(br + 8*p)*132 + bc], &W[(size_t)(br + 8*p)*N + n0 + bc]);
    cp_commit();

    for (int k0 = 0; k0 < K; k0 += 32) {
        cp_wait<0>();
        __syncthreads();
        const int s = (k0 >> 5) & 1;
        if (k0 + 32 < K) {
            float* An = As + (s ^ 1) * 128 * 36;
            float* Bn = Bs + (s ^ 1) * 32 * 132;
            #pragma unroll
            for (int p = 0; p < 4; p++)
                cp_async16(&An[(ar + 32*p)*36 + ac],
                           &A[(size_t)(m0 + ar + 32*p)*K + k0 + 32 + ac]);
            #pragma unroll
            for (int p = 0; p < 4; p++)
                cp_async16(&Bn[(br + 8*p)*132 + bc],
                           &W[(size_t)(k0 + 32 + br + 8*p)*N + n0 + bc]);
            cp_commit();
        }
        const float* Ac = As + s * 128 * 36;
        const float* Bc = Bs + s * 32 * 132;
        #pragma unroll
        for (int ks = 0; ks < 4; ks++) {
            const int kk = ks * 8 + tg;
            uint32_t a[4][4], b[4][2];
            #pragma unroll
            for (int mt = 0; mt < 4; mt++) {
                int m = wm + mt * 16 + g;
                a[mt][0] = *(const uint32_t*)&Ac[m*36 + kk];
                a[mt][1] = *(const uint32_t*)&Ac[(m+8)*36 + kk];
                a[mt][2] = *(const uint32_t*)&Ac[m*36 + kk + 4];
                a[mt][3] = *(const uint32_t*)&Ac[(m+8)*36 + kk + 4];
            }
            #pragma unroll
            for (int nt = 0; nt < 4; nt++) {
                int n = wn + nt * 8 + g;
                b[nt][0] = *(const uint32_t*)&Bc[kk*132 + n];
                b[nt][1] = *(const uint32_t*)&Bc[(kk+4)*132 + n];
            }
            #pragma unroll
            for (int mt = 0; mt < 4; mt++)
                #pragma unroll
                for (int nt = 0; nt < 4; nt++)
                    mma_tf32(acc[mt][nt], a[mt], b[nt]);
        }
        // no trailing sync: next iteration's wait+sync protects buffer reuse
    }

    // Epilogue
    #pragma unroll
    for (int mt = 0; mt < 4; mt++) {
        #pragma unroll
        for (int nt = 0; nt < 4; nt++) {
            int n  = n0 + wn + nt * 8 + 2 * tg;
            float b0v = bias[n], b1v = bias[n + 1];
            #pragma unroll
            for (int half = 0; half < 2; half++) {
                int m = m0 + wm + mt * 16 + g + half * 8;
                float2 v;
                v.x = acc[mt][nt][half*2 + 0] + b0v;
                v.y = acc[mt][nt][half*2 + 1] + b1v;
                if (REMAP) {
                    v.x = to_tf32(v.x); v.y = to_tf32(v.y);   // flash consumes raw
                    int bb = m >> 11, ss = m & 2047, h = n >> 6, d = n & 63;
                    *(float2*)&C[((((size_t)bb*NHEADS + h)*SEQ + ss) << 6) + d] = v;
                } else {
                    *(float2*)&C[(size_t)m * N + n] = v;
                }
            }
        }
    }
}

// ---------------------------------------------------------------------------
// Causal flash attention, tf32, register-resident softmax.
// CTA = 256 threads (8 warps) on a 128q x 64k tile; warp tile = 16q x 64k
// (warp owns complete rows => softmax via quad shuffles, m/l in registers).
// Q/K/V pre-rounded to tf32 (cp.async raw). K/V double-buffered.
// ---------------------------------------------------------------------------
#define QLD 68
#define VLD 72
#define FLASH_SMEM ((128*QLD + 128*QLD + 2*64*QLD + 2*64*VLD) * 4)

__global__ __launch_bounds__(256, 1)
void flash_tf32(const float* __restrict__ Q, const float* __restrict__ K,
                const float* __restrict__ V, float* __restrict__ ctx)
{
    extern __shared__ float sm[];
    float* Qs = sm;                      // [128][68]
    float* Ps = sm + 128 * QLD;          // [128][68]
    float* Ks = sm + 2 * 128 * QLD;      // [2][64][68]
    float* Vs = Ks + 2 * 64 * QLD;       // [2][64][72]

    const int t    = threadIdx.x;
    const int lane = t & 31;
    const int warp = t >> 5;
    const int g    = lane >> 2;
    const int tg   = lane & 3;
    const int wq   = warp * 16;          // this warp's 16 query rows
    const int qt   = blockIdx.x;         // 0..15
    const int bh   = blockIdx.y;         // 0..63
    const int q0   = qt * 128;
    const int kt_max = 2 * qt + 1;
    const float scl = 0.125f;            // 1/sqrt(64), applied post-mma (exact)

    const int lr = t >> 4, lc = (t & 15) * 4;   // cooperative load indices

    // Q tile (raw, pre-rounded)
    {
        const float* Qb = Q + ((size_t)bh * SEQ + q0) * HDIM;
        #pragma unroll
        for (int p = 0; p < 8; p++)
            cp_async16(&Qs[(lr + 16*p)*QLD + lc], &Qb[(lr + 16*p)*HDIM + lc]);
    }
    // K/V tile 0
    {
        const float* Kb = K + (size_t)bh * SEQ * HDIM;
        const float* Vb = V + (size_t)bh * SEQ * HDIM;
        #pragma unroll
        for (int p = 0; p < 4; p++) {
            cp_async16(&Ks[(lr + 16*p)*QLD + lc], &Kb[(lr + 16*p)*HDIM + lc]);
            cp_async16(&Vs[(lr + 16*p)*VLD + lc], &Vb[(lr + 16*p)*HDIM + lc]);
        }
    }
    cp_commit();

    float m0r = -INFINITY, m1r = -INFINITY;
    float l0r = 0.f, l1r = 0.f;
    float o[8][4] = {};

    const int row0 = q0 + wq + g;
    const int row1 = row0 + 8;

    for (int kt = 0; kt <= kt_max; kt++) {
        cp_wait<0>();
        __syncthreads();
        const int s = kt & 1;
        if (kt < kt_max) {
            const int kn = (kt + 1) * 64;
            const float* Kb = K + ((size_t)bh * SEQ + kn) * HDIM;
            const float* Vb = V + ((size_t)bh * SEQ + kn) * HDIM;
            float* Kn = Ks + (s ^ 1) * 64 * QLD;
            float* Vn = Vs + (s ^ 1) * 64 * VLD;
            #pragma unroll
            for (int p = 0; p < 4; p++) {
                cp_async16(&Kn[(lr + 16*p)*QLD + lc], &Kb[(lr + 16*p)*HDIM + lc]);
                cp_async16(&Vn[(lr + 16*p)*VLD + lc], &Vb[(lr + 16*p)*HDIM + lc]);
            }
            cp_commit();
        }
        const float* Kc = Ks + s * 64 * QLD;
        const float* Vc = Vs + s * 64 * VLD;
        const int k0 = kt * 64;

        // ---- S = Q K^T ----
        float sc[8][4] = {};
        #pragma unroll
        for (int ks = 0; ks < 8; ks++) {
            const int kk = ks * 8 + tg;
            uint32_t a[4], b[8][2];
            a[0] = *(const uint32_t*)&Qs[(wq + g)*QLD + kk];
            a[1] = *(const uint32_t*)&Qs[(wq + g + 8)*QLD + kk];
            a[2] = *(const uint32_t*)&Qs[(wq + g)*QLD + kk + 4];
            a[3] = *(const uint32_t*)&Qs[(wq + g + 8)*QLD + kk + 4];
            #pragma unroll
            for (int nt = 0; nt < 8; nt++) {
                int n = nt * 8 + g;
                b[nt][0] = *(const uint32_t*)&Kc[n*QLD + kk];
                b[nt][1] = *(const uint32_t*)&Kc[n*QLD + kk + 4];
            }
            #pragma unroll
            for (int nt = 0; nt < 8; nt++)
                mma_tf32(sc[nt], a, b[nt]);
        }

        // ---- scale + causal mask ----
        if (k0 + 63 > row0) {
            #pragma unroll
            for (int nt = 0; nt < 8; nt++) {
                int c = k0 + nt * 8 + 2 * tg;
                sc[nt][0] = (c     > row0) ? -INFINITY : sc[nt][0] * scl;
                sc[nt][1] = (c + 1 > row0) ? -INFINITY : sc[nt][1] * scl;
                sc[nt][2] = (c     > row1) ? -INFINITY : sc[nt][2] * scl;
                sc[nt][3] = (c + 1 > row1) ? -INFINITY : sc[nt][3] * scl;
            }
        } else {
            #pragma unroll
            for (int nt = 0; nt < 8; nt++)
                #pragma unroll
                for (int i = 0; i < 4; i++) sc[nt][i] *= scl;
        }

        // ---- row max (registers + quad shuffle) ----
        float mx0 = -INFINITY, mx1 = -INFINITY;
        #pragma unroll
        for (int nt = 0; nt < 8; nt++) {
            mx0 = fmaxf(mx0, fmaxf(sc[nt][0], sc[nt][1]));
            mx1 = fmaxf(mx1, fmaxf(sc[nt][2], sc[nt][3]));
        }
        mx0 = fmaxf(mx0, __shfl_xor_sync(0xffffffff, mx0, 1));
        mx0 = fmaxf(mx0, __shfl_xor_sync(0xffffffff, mx0, 2));
        mx1 = fmaxf(mx1, __shfl_xor_sync(0xffffffff, mx1, 1));
        mx1 = fmaxf(mx1, __shfl_xor_sync(0xffffffff, mx1, 2));

        float mn0 = fmaxf(m0r, mx0), mn1 = fmaxf(m1r, mx1);
        float al0 = __expf(m0r - mn0), al1 = __expf(m1r - mn1);
        m0r = mn0; m1r = mn1;

        // ---- exp (tf32-rounded), row sums, write P, rescale O ----
        float s0 = 0.f, s1 = 0.f;
        #pragma unroll
        for (int nt = 0; nt < 8; nt++) {
            float p0 = to_tf32(__expf(sc[nt][0] - mn0));
            float p1 = to_tf32(__expf(sc[nt][1] - mn0));
            float p2 = to_tf32(__expf(sc[nt][2] - mn1));
            float p3 = to_tf32(__expf(sc[nt][3] - mn1));
            s0 += p0 + p1;
            s1 += p2 + p3;
            int c = nt * 8 + 2 * tg;
            *(float2*)&Ps[(wq + g)*QLD + c]     = make_float2(p0, p1);
            *(float2*)&Ps[(wq + g + 8)*QLD + c] = make_float2(p2, p3);
        }
        s0 += __shfl_xor_sync(0xffffffff, s0, 1);
        s0 += __shfl_xor_sync(0xffffffff, s0, 2);
        s1 += __shfl_xor_sync(0xffffffff, s1, 1);
        s1 += __shfl_xor_sync(0xffffffff, s1, 2);
        l0r = l0r * al0 + s0;
        l1r = l1r * al1 + s1;
        #pragma unroll
        for (int nt = 0; nt < 8; nt++) {
            o[nt][0] *= al0; o[nt][1] *= al0;
            o[nt][2] *= al1; o[nt][3] *= al1;
        }
        __syncwarp();   // P tile is warp-private: warp barrier suffices

        // ---- O += P V ----
        #pragma unroll
        for (int ks = 0; ks < 8; ks++) {
            const int kk = ks * 8 + tg;
            uint32_t a[4], b[8][2];
            a[0] = *(const uint32_t*)&Ps[(wq + g)*QLD + kk];
            a[1] = *(const uint32_t*)&Ps[(wq + g + 8)*QLD + kk];
            a[2] = *(const uint32_t*)&Ps[(wq + g)*QLD + kk + 4];
            a[3] = *(const uint32_t*)&Ps[(wq + g + 8)*QLD + kk + 4];
            #pragma unroll
            for (int nt = 0; nt < 8; nt++) {
                int n = nt * 8 + g;
                b[nt][0] = *(const uint32_t*)&Vc[kk*VLD + n];
                b[nt][1] = *(const uint32_t*)&Vc[(kk+4)*VLD + n];
            }
            #pragma unroll
            for (int nt = 0; nt < 8; nt++)
                mma_tf32(o[nt], a, b[nt]);
        }
    }

    // Epilogue: normalize, tf32-round (consumed by O-proj GEMM), write ctx
    const int bb = bh >> 4;
    const int h  = bh & 15;
    const float il0 = 1.f / l0r, il1 = 1.f / l1r;
    #pragma unroll
    for (int nt = 0; nt < 8; nt++) {
        int d = nt * 8 + 2 * tg;
        float2 v;
        v.x = to_tf32(o[nt][0] * il0);
        v.y = to_tf32(o[nt][1] * il0);
        *(float2*)&ctx[((size_t)bb*SEQ + row0)*D_MODEL + h*HDIM + d] = v;
        v.x = to_tf32(o[nt][2] * il1);
        v.y = to_tf32(o[nt][3] * il1);
        *(float2*)&ctx[((size_t)bb*SEQ + row1)*D_MODEL + h*HDIM + d] = v;
    }
}

// ---------------------------------------------------------------------------
extern "C" void kernel_launch(void* const* d_in, const int* in_sizes, int n_in,
                              void* d_out, int out_size)
{
    const float* in_q = (const float*)d_in[0];
    const float* in_k = (const float*)d_in[1];
    const float* in_v = (const float*)d_in[2];
    const float* Wq   = (const float*)d_in[3];
    const float* bq   = (const float*)d_in[4];
    const float* Wk   = (const float*)d_in[5];
    const float* bk   = (const float*)d_in[6];
    const float* Wv   = (const float*)d_in[7];
    const float* bv   = (const float*)d_in[8];
    const float* Wo   = (const float*)d_in[9];
    const float* bo   = (const float*)d_in[10];
    float* out = (float*)d_out;

    float *gq, *gk, *gv, *gc, *aq, *ak, *av, *wq, *wk, *wv, *wo;
    cudaGetSymbolAddress((void**)&gq, g_Q);
    cudaGetSymbolAddress((void**)&gk, g_K);
    cudaGetSymbolAddress((void**)&gv, g_V);
    cudaGetSymbolAddress((void**)&gc, g_C);
    cudaGetSymbolAddress((void**)&aq, g_Aq);
    cudaGetSymbolAddress((void**)&ak, g_Ak);
    cudaGetSymbolAddress((void**)&av, g_Av);
    cudaGetSymbolAddress((void**)&wq, g_Wq);
    cudaGetSymbolAddress((void**)&wk, g_Wk);
    cudaGetSymbolAddress((void**)&wv, g_Wv);
    cudaGetSymbolAddress((void**)&wo, g_Wo);

    static int attr_set = 0;
    if (!attr_set) {
        cudaFuncSetAttribute(gemm_tf32<0>, cudaFuncAttributeMaxDynamicSharedMemorySize, GEMM_SMEM);
        cudaFuncSetAttribute(gemm_tf32<1>, cudaFuncAttributeMaxDynamicSharedMemorySize, GEMM_SMEM);
        cudaFuncSetAttribute(flash_tf32, cudaFuncAttributeMaxDynamicSharedMemorySize, FLASH_SMEM);
        attr_set = 1;
    }

    // Prepass: tf32-round activations + weights (bit-exact relocation of cvt)
    const int nA4 = MROWS * D_MODEL / 4;     // 2M
    const int nW4 = D_MODEL * D_MODEL / 4;   // 256K
    cvt_tf32_kernel<<<(nA4 + 255)/256, 256>>>((const float4*)in_q, (float4*)aq, nA4);
    cvt_tf32_kernel<<<(nA4 + 255)/256, 256>>>((const float4*)in_k, (float4*)ak, nA4);
    cvt_tf32_kernel<<<(nA4 + 255)/256, 256>>>((const float4*)in_v, (float4*)av, nA4);
    cvt_tf32_kernel<<<(nW4 + 255)/256, 256>>>((const float4*)Wq, (float4*)wq, nW4);
    cvt_tf32_kernel<<<(nW4 + 255)/256, 256>>>((const float4*)Wk, (float4*)wk, nW4);
    cvt_tf32_kernel<<<(nW4 + 255)/256, 256>>>((const float4*)Wv, (float4*)wv, nW4);
    cvt_tf32_kernel<<<(nW4 + 255)/256, 256>>>((const float4*)Wo, (float4*)wo, nW4);

    dim3 gemm_grid(D_MODEL / 128, MROWS / 128);  // (8, 64)
    gemm_tf32<1><<<gemm_grid, 256, GEMM_SMEM>>>(aq, wq, bq, gq);
    gemm_tf32<1><<<gemm_grid, 256, GEMM_SMEM>>>(ak, wk, bk, gk);
    gemm_tf32<1><<<gemm_grid, 256, GEMM_SMEM>>>(av, wv, bv, gv);

    dim3 attn_grid(SEQ / 128, BATCH * NHEADS);   // (16, 64)
    flash_tf32<<<attn_grid, 256, FLASH_SMEM>>>(gq, gk, gv, gc);

    gemm_tf32<0><<<gemm_grid, 256, GEMM_SMEM>>>(gc, wo, bo, out);
}

// round 7
// speedup vs baseline: 4.0007x; 1.0890x over previous
#include <cuda_runtime.h>
#include <math.h>
#include <stdint.h>

#define D_MODEL 1024
#define NHEADS  16
#define HDIM    64
#define BATCH   4
#define SEQ     2048
#define MROWS   (BATCH*SEQ)   // 8192

// Scratch (device globals — no allocations allowed)
__device__ float g_Q[(size_t)MROWS * D_MODEL];
__device__ float g_K[(size_t)MROWS * D_MODEL];
__device__ float g_V[(size_t)MROWS * D_MODEL];
__device__ float g_C[(size_t)MROWS * D_MODEL];
// tf32-prerounded weights
__device__ float g_Wq[(size_t)D_MODEL * D_MODEL];
__device__ float g_Wk[(size_t)D_MODEL * D_MODEL];
__device__ float g_Wv[(size_t)D_MODEL * D_MODEL];
__device__ float g_Wo[(size_t)D_MODEL * D_MODEL];

__device__ __forceinline__ float to_tf32(float x) {
    asm("cvt.rna.tf32.f32 %0, %0;" : "+f"(x));
    return x;
}

__device__ __forceinline__ void mma_tf32(float c[4], const uint32_t a[4], const uint32_t b[2]) {
    asm volatile(
        "mma.sync.aligned.m16n8k8.row.col.f32.tf32.tf32.f32 "
        "{%0,%1,%2,%3},{%4,%5,%6,%7},{%8,%9},{%0,%1,%2,%3};"
        : "+f"(c[0]), "+f"(c[1]), "+f"(c[2]), "+f"(c[3])
        : "r"(a[0]), "r"(a[1]), "r"(a[2]), "r"(a[3]), "r"(b[0]), "r"(b[1]));
}

__device__ __forceinline__ void cp_async16(void* sptr, const void* gptr) {
    uint32_t s = (uint32_t)__cvta_generic_to_shared(sptr);
    asm volatile("cp.async.cg.shared.global [%0], [%1], 16;" :: "r"(s), "l"(gptr));
}
__device__ __forceinline__ void cp_commit() { asm volatile("cp.async.commit_group;"); }
template<int N> __device__ __forceinline__ void cp_wait() {
    asm volatile("cp.async.wait_group %0;" :: "n"(N));
}

// ---------------------------------------------------------------------------
// Fused weight prepass: tf32-round all 4 weight matrices (grid.z selects).
// ---------------------------------------------------------------------------
__global__ void cvt_w_kernel(const float4* __restrict__ w0, float4* __restrict__ o0,
                             const float4* __restrict__ w1, float4* __restrict__ o1,
                             const float4* __restrict__ w2, float4* __restrict__ o2,
                             const float4* __restrict__ w3, float4* __restrict__ o3,
                             int n4)
{
    const float4* in;
    float4* out;
    switch (blockIdx.z) {
        case 0: in = w0; out = o0; break;
        case 1: in = w1; out = o1; break;
        case 2: in = w2; out = o2; break;
        default: in = w3; out = o3; break;
    }
    int i = blockIdx.x * blockDim.x + threadIdx.x;
    if (i < n4) {
        float4 v = in[i];
        v.x = to_tf32(v.x); v.y = to_tf32(v.y);
        v.z = to_tf32(v.z); v.w = to_tf32(v.w);
        out[i] = v;
    }
}

#define GEMM_SMEM ((2*128*36 + 2*32*132) * 4)

// ---------------------------------------------------------------------------
// Fused QKV projection GEMM (grid.z = 3 selects Q/K/V problem).
// A = raw fp32 activations: LDG -> cvt.rna -> STS register-staged pipeline.
// W = pre-rounded tf32 weights via cp.async double buffer.
// Epilogue: bias, tf32-round, head-split store [B,H,S,HDIM].
// ---------------------------------------------------------------------------
__global__ __launch_bounds__(256, 2)
void gemm_qkv(const float* __restrict__ A0, const float* __restrict__ W0,
              const float* __restrict__ b0p, float* __restrict__ C0,
              const float* __restrict__ A1, const float* __restrict__ W1,
              const float* __restrict__ b1p, float* __restrict__ C1,
              const float* __restrict__ A2, const float* __restrict__ W2,
              const float* __restrict__ b2p, float* __restrict__ C2)
{
    const int K = D_MODEL, N = D_MODEL;
    extern __shared__ float smem[];
    float* As = smem;                 // [2][128][36]
    float* Bs = smem + 2 * 128 * 36;  // [2][32][132]

    const float *A, *W, *bias;
    float* C;
    switch (blockIdx.z) {
        case 0:  A = A0; W = W0; bias = b0p; C = C0; break;
        case 1:  A = A1; W = W1; bias = b1p; C = C1; break;
        default: A = A2; W = W2; bias = b2p; C = C2; break;
    }

    const int t    = threadIdx.x;
    const int lane = t & 31;
    const int warp = t >> 5;
    const int g    = lane >> 2;
    const int tg   = lane & 3;
    const int wm   = (warp & 1) * 64;
    const int wn   = (warp >> 1) * 32;
    const int m0   = blockIdx.y * 128;
    const int n0   = blockIdx.x * 128;

    const int ar = t >> 3, ac = (t & 7) * 4;
    const int br = t >> 5, bc = (t & 31) * 4;

    float acc[4][4][4] = {};
    float4 areg[4];

    // Prologue: LDG A(k0=0) to regs, cp.async B stage0
    #pragma unroll
    for (int p = 0; p < 4; p++)
        areg[p] = *(const float4*)&A[(size_t)(m0 + ar + 32*p)*K + ac];
    #pragma unroll
    for (int p = 0; p < 4; p++)
        cp_async16(&Bs[(br + 8*p)*132 + bc], &W[(size_t)(br + 8*p)*N + n0 + bc]);
    cp_commit();
    // cvt + STS A stage0
    #pragma unroll
    for (int p = 0; p < 4; p++) {
        float4 v = areg[p];
        v.x = to_tf32(v.x); v.y = to_tf32(v.y);
        v.z = to_tf32(v.z); v.w = to_tf32(v.w);
        *(float4*)&As[(ar + 32*p)*36 + ac] = v;
    }

    for (int k0 = 0; k0 < K; k0 += 32) {
        cp_wait<0>();
        __syncthreads();
        const int s = (k0 >> 5) & 1;
        const bool more = (k0 + 32 < K);
        if (more) {
            // LDG next A tile (consumed at loop end — latency covered by mma)
            #pragma unroll
            for (int p = 0; p < 4; p++)
                areg[p] = *(const float4*)&A[(size_t)(m0 + ar + 32*p)*K + k0 + 32 + ac];
            float* Bn = Bs + (s ^ 1) * 32 * 132;
            #pragma unroll
            for (int p = 0; p < 4; p++)
                cp_async16(&Bn[(br + 8*p)*132 + bc],
                           &W[(size_t)(k0 + 32 + br + 8*p)*N + n0 + bc]);
            cp_commit();
        }
        const float* Ac = As + s * 128 * 36;
        const float* Bc = Bs + s * 32 * 132;
        #pragma unroll
        for (int ks = 0; ks < 4; ks++) {
            const int kk = ks * 8 + tg;
            uint32_t a[4][4], b[4][2];
            #pragma unroll
            for (int mt = 0; mt < 4; mt++) {
                int m = wm + mt * 16 + g;
                a[mt][0] = *(const uint32_t*)&Ac[m*36 + kk];
                a[mt][1] = *(const uint32_t*)&Ac[(m+8)*36 + kk];
                a[mt][2] = *(const uint32_t*)&Ac[m*36 + kk + 4];
                a[mt][3] = *(const uint32_t*)&Ac[(m+8)*36 + kk + 4];
            }
            #pragma unroll
            for (int nt = 0; nt < 4; nt++) {
                int n = wn + nt * 8 + g;
                b[nt][0] = *(const uint32_t*)&Bc[kk*132 + n];
                b[nt][1] = *(const uint32_t*)&Bc[(kk+4)*132 + n];
            }
            #pragma unroll
            for (int mt = 0; mt < 4; mt++)
                #pragma unroll
                for (int nt = 0; nt < 4; nt++)
                    mma_tf32(acc[mt][nt], a[mt], b[nt]);
        }
        if (more) {
            float* An = As + (s ^ 1) * 128 * 36;
            #pragma unroll
            for (int p = 0; p < 4; p++) {
                float4 v = areg[p];
                v.x = to_tf32(v.x); v.y = to_tf32(v.y);
                v.z = to_tf32(v.z); v.w = to_tf32(v.w);
                *(float4*)&An[(ar + 32*p)*36 + ac] = v;
            }
        }
    }

    // Epilogue: bias + tf32-round + head-split store
    #pragma unroll
    for (int mt = 0; mt < 4; mt++) {
        #pragma unroll
        for (int nt = 0; nt < 4; nt++) {
            int n  = n0 + wn + nt * 8 + 2 * tg;
            float b0v = bias[n], b1v = bias[n + 1];
            #pragma unroll
            for (int half = 0; half < 2; half++) {
                int m = m0 + wm + mt * 16 + g + half * 8;
                float2 v;
                v.x = to_tf32(acc[mt][nt][half*2 + 0] + b0v);
                v.y = to_tf32(acc[mt][nt][half*2 + 1] + b1v);
                int bb = m >> 11, ss = m & 2047, h = n >> 6, d = n & 63;
                *(float2*)&C[((((size_t)bb*NHEADS + h)*SEQ + ss) << 6) + d] = v;
            }
        }
    }
}

// ---------------------------------------------------------------------------
// O-projection GEMM: both A (already tf32-rounded ctx) and W via cp.async.
// ---------------------------------------------------------------------------
__global__ __launch_bounds__(256, 2)
void gemm_oproj(const float* __restrict__ A, const float* __restrict__ W,
                const float* __restrict__ bias, float* __restrict__ C)
{
    const int K = D_MODEL, N = D_MODEL;
    extern __shared__ float smem[];
    float* As = smem;                 // [2][128][36]
    float* Bs = smem + 2 * 128 * 36;  // [2][32][132]

    const int t    = threadIdx.x;
    const int lane = t & 31;
    const int warp = t >> 5;
    const int g    = lane >> 2;
    const int tg   = lane & 3;
    const int wm   = (warp & 1) * 64;
    const int wn   = (warp >> 1) * 32;
    const int m0   = blockIdx.y * 128;
    const int n0   = blockIdx.x * 128;

    const int ar = t >> 3, ac = (t & 7) * 4;
    const int br = t >> 5, bc = (t & 31) * 4;

    float acc[4][4][4] = {};

    #pragma unroll
    for (int p = 0; p < 4; p++)
        cp_async16(&As[(ar + 32*p)*36 + ac], &A[(size_t)(m0 + ar + 32*p)*K + ac]);
    #pragma unroll
    for (int p = 0; p < 4; p++)
        cp_async16(&Bs[(br + 8*p)*132 + bc], &W[(size_t)(br + 8*p)*N + n0 + bc]);
    cp_commit();

    for (int k0 = 0; k0 < K; k0 += 32) {
        cp_wait<0>();
        __syncthreads();
        const int s = (k0 >> 5) & 1;
        if (k0 + 32 < K) {
            float* An = As + (s ^ 1) * 128 * 36;
            float* Bn = Bs + (s ^ 1) * 32 * 132;
            #pragma unroll
            for (int p = 0; p < 4; p++)
                cp_async16(&An[(ar + 32*p)*36 + ac],
                           &A[(size_t)(m0 + ar + 32*p)*K + k0 + 32 + ac]);
            #pragma unroll
            for (int p = 0; p < 4; p++)
                cp_async16(&Bn[(br + 8*p)*132 + bc],
                           &W[(size_t)(k0 + 32 + br + 8*p)*N + n0 + bc]);
            cp_commit();
        }
        const float* Ac = As + s * 128 * 36;
        const float* Bc = Bs + s * 32 * 132;
        #pragma unroll
        for (int ks = 0; ks < 4; ks++) {
            const int kk = ks * 8 + tg;
            uint32_t a[4][4], b[4][2];
            #pragma unroll
            for (int mt = 0; mt < 4; mt++) {
                int m = wm + mt * 16 + g;
                a[mt][0] = *(const uint32_t*)&Ac[m*36 + kk];
                a[mt][1] = *(const uint32_t*)&Ac[(m+8)*36 + kk];
                a[mt][2] = *(const uint32_t*)&Ac[m*36 + kk + 4];
                a[mt][3] = *(const uint32_t*)&Ac[(m+8)*36 + kk + 4];
            }
            #pragma unroll
            for (int nt = 0; nt < 4; nt++) {
                int n = wn + nt * 8 + g;
                b[nt][0] = *(const uint32_t*)&Bc[kk*132 + n];
                b[nt][1] = *(const uint32_t*)&Bc[(kk+4)*132 + n];
            }
            #pragma unroll
            for (int mt = 0; mt < 4; mt++)
                #pragma unroll
                for (int nt = 0; nt < 4; nt++)
                    mma_tf32(acc[mt][nt], a[mt], b[nt]);
        }
    }

    #pragma unroll
    for (int mt = 0; mt < 4; mt++) {
        #pragma unroll
        for (int nt = 0; nt < 4; nt++) {
            int n  = n0 + wn + nt * 8 + 2 * tg;
            float b0v = bias[n], b1v = bias[n + 1];
            #pragma unroll
            for (int half = 0; half < 2; half++) {
                int m = m0 + wm + mt * 16 + g + half * 8;
                float2 v;
                v.x = acc[mt][nt][half*2 + 0] + b0v;
                v.y = acc[mt][nt][half*2 + 1] + b1v;
                *(float2*)&C[(size_t)m * N + n] = v;
            }
        }
    }
}

// ---------------------------------------------------------------------------
// Causal flash attention, tf32, register-resident softmax. (unchanged)
// ---------------------------------------------------------------------------
#define QLD 68
#define VLD 72
#define FLASH_SMEM ((128*QLD + 128*QLD + 2*64*QLD + 2*64*VLD) * 4)

__global__ __launch_bounds__(256, 1)
void flash_tf32(const float* __restrict__ Q, const float* __restrict__ K,
                const float* __restrict__ V, float* __restrict__ ctx)
{
    extern __shared__ float sm[];
    float* Qs = sm;                      // [128][68]
    float* Ps = sm + 128 * QLD;          // [128][68]
    float* Ks = sm + 2 * 128 * QLD;      // [2][64][68]
    float* Vs = Ks + 2 * 64 * QLD;       // [2][64][72]

    const int t    = threadIdx.x;
    const int lane = t & 31;
    const int warp = t >> 5;
    const int g    = lane >> 2;
    const int tg   = lane & 3;
    const int wq   = warp * 16;
    const int qt   = blockIdx.x;
    const int bh   = blockIdx.y;
    const int q0   = qt * 128;
    const int kt_max = 2 * qt + 1;
    const float scl = 0.125f;

    const int lr = t >> 4, lc = (t & 15) * 4;

    {
        const float* Qb = Q + ((size_t)bh * SEQ + q0) * HDIM;
        #pragma unroll
        for (int p = 0; p < 8; p++)
            cp_async16(&Qs[(lr + 16*p)*QLD + lc], &Qb[(lr + 16*p)*HDIM + lc]);
    }
    {
        const float* Kb = K + (size_t)bh * SEQ * HDIM;
        const float* Vb = V + (size_t)bh * SEQ * HDIM;
        #pragma unroll
        for (int p = 0; p < 4; p++) {
            cp_async16(&Ks[(lr + 16*p)*QLD + lc], &Kb[(lr + 16*p)*HDIM + lc]);
            cp_async16(&Vs[(lr + 16*p)*VLD + lc], &Vb[(lr + 16*p)*HDIM + lc]);
        }
    }
    cp_commit();

    float m0r = -INFINITY, m1r = -INFINITY;
    float l0r = 0.f, l1r = 0.f;
    float o[8][4] = {};

    const int row0 = q0 + wq + g;
    const int row1 = row0 + 8;

    for (int kt = 0; kt <= kt_max; kt++) {
        cp_wait<0>();
        __syncthreads();
        const int s = kt & 1;
        if (kt < kt_max) {
            const int kn = (kt + 1) * 64;
            const float* Kb = K + ((size_t)bh * SEQ + kn) * HDIM;
            const float* Vb = V + ((size_t)bh * SEQ + kn) * HDIM;
            float* Kn = Ks + (s ^ 1) * 64 * QLD;
            float* Vn = Vs + (s ^ 1) * 64 * VLD;
            #pragma unroll
            for (int p = 0; p < 4; p++) {
                cp_async16(&Kn[(lr + 16*p)*QLD + lc], &Kb[(lr + 16*p)*HDIM + lc]);
                cp_async16(&Vn[(lr + 16*p)*VLD + lc], &Vb[(lr + 16*p)*HDIM + lc]);
            }
            cp_commit();
        }
        const float* Kc = Ks + s * 64 * QLD;
        const float* Vc = Vs + s * 64 * VLD;
        const int k0 = kt * 64;

        float sc[8][4] = {};
        #pragma unroll
        for (int ks = 0; ks < 8; ks++) {
            const int kk = ks * 8 + tg;
            uint32_t a[4], b[8][2];
            a[0] = *(const uint32_t*)&Qs[(wq + g)*QLD + kk];
            a[1] = *(const uint32_t*)&Qs[(wq + g + 8)*QLD + kk];
            a[2] = *(const uint32_t*)&Qs[(wq + g)*QLD + kk + 4];
            a[3] = *(const uint32_t*)&Qs[(wq + g + 8)*QLD + kk + 4];
            #pragma unroll
            for (int nt = 0; nt < 8; nt++) {
                int n = nt * 8 + g;
                b[nt][0] = *(const uint32_t*)&Kc[n*QLD + kk];
                b[nt][1] = *(const uint32_t*)&Kc[n*QLD + kk + 4];
            }
            #pragma unroll
            for (int nt = 0; nt < 8; nt++)
                mma_tf32(sc[nt], a, b[nt]);
        }

        if (k0 + 63 > row0) {
            #pragma unroll
            for (int nt = 0; nt < 8; nt++) {
                int c = k0 + nt * 8 + 2 * tg;
                sc[nt][0] = (c     > row0) ? -INFINITY : sc[nt][0] * scl;
                sc[nt][1] = (c + 1 > row0) ? -INFINITY : sc[nt][1] * scl;
                sc[nt][2] = (c     > row1) ? -INFINITY : sc[nt][2] * scl;
                sc[nt][3] = (c + 1 > row1) ? -INFINITY : sc[nt][3] * scl;
            }
        } else {
            #pragma unroll
            for (int nt = 0; nt < 8; nt++)
                #pragma unroll
                for (int i = 0; i < 4; i++) sc[nt][i] *= scl;
        }

        float mx0 = -INFINITY, mx1 = -INFINITY;
        #pragma unroll
        for (int nt = 0; nt < 8; nt++) {
            mx0 = fmaxf(mx0, fmaxf(sc[nt][0], sc[nt][1]));
            mx1 = fmaxf(mx1, fmaxf(sc[nt][2], sc[nt][3]));
        }
        mx0 = fmaxf(mx0, __shfl_xor_sync(0xffffffff, mx0, 1));
        mx0 = fmaxf(mx0, __shfl_xor_sync(0xffffffff, mx0, 2));
        mx1 = fmaxf(mx1, __shfl_xor_sync(0xffffffff, mx1, 1));
        mx1 = fmaxf(mx1, __shfl_xor_sync(0xffffffff, mx1, 2));

        float mn0 = fmaxf(m0r, mx0), mn1 = fmaxf(m1r, mx1);
        float al0 = __expf(m0r - mn0), al1 = __expf(m1r - mn1);
        m0r = mn0; m1r = mn1;

        float s0 = 0.f, s1 = 0.f;
        #pragma unroll
        for (int nt = 0; nt < 8; nt++) {
            float p0 = to_tf32(__expf(sc[nt][0] - mn0));
            float p1 = to_tf32(__expf(sc[nt][1] - mn0));
            float p2 = to_tf32(__expf(sc[nt][2] - mn1));
            float p3 = to_tf32(__expf(sc[nt][3] - mn1));
            s0 += p0 + p1;
            s1 += p2 + p3;
            int c = nt * 8 + 2 * tg;
            *(float2*)&Ps[(wq + g)*QLD + c]     = make_float2(p0, p1);
            *(float2*)&Ps[(wq + g + 8)*QLD + c] = make_float2(p2, p3);
        }
        s0 += __shfl_xor_sync(0xffffffff, s0, 1);
        s0 += __shfl_xor_sync(0xffffffff, s0, 2);
        s1 += __shfl_xor_sync(0xffffffff, s1, 1);
        s1 += __shfl_xor_sync(0xffffffff, s1, 2);
        l0r = l0r * al0 + s0;
        l1r = l1r * al1 + s1;
        #pragma unroll
        for (int nt = 0; nt < 8; nt++) {
            o[nt][0] *= al0; o[nt][1] *= al0;
            o[nt][2] *= al1; o[nt][3] *= al1;
        }
        __syncwarp();

        #pragma unroll
        for (int ks = 0; ks < 8; ks++) {
            const int kk = ks * 8 + tg;
            uint32_t a[4], b[8][2];
            a[0] = *(const uint32_t*)&Ps[(wq + g)*QLD + kk];
            a[1] = *(const uint32_t*)&Ps[(wq + g + 8)*QLD + kk];
            a[2] = *(const uint32_t*)&Ps[(wq + g)*QLD + kk + 4];
            a[3] = *(const uint32_t*)&Ps[(wq + g + 8)*QLD + kk + 4];
            #pragma unroll
            for (int nt = 0; nt < 8; nt++) {
                int n = nt * 8 + g;
                b[nt][0] = *(const uint32_t*)&Vc[kk*VLD + n];
                b[nt][1] = *(const uint32_t*)&Vc[(kk+4)*VLD + n];
            }
            #pragma unroll
            for (int nt = 0; nt < 8; nt++)
                mma_tf32(o[nt], a, b[nt]);
        }
    }

    const int bb = bh >> 4;
    const int h  = bh & 15;
    const float il0 = 1.f / l0r, il1 = 1.f / l1r;
    #pragma unroll
    for (int nt = 0; nt < 8; nt++) {
        int d = nt * 8 + 2 * tg;
        float2 v;
        v.x = to_tf32(o[nt][0] * il0);
        v.y = to_tf32(o[nt][1] * il0);
        *(float2*)&ctx[((size_t)bb*SEQ + row0)*D_MODEL + h*HDIM + d] = v;
        v.x = to_tf32(o[nt][2] * il1);
        v.y = to_tf32(o[nt][3] * il1);
        *(float2*)&ctx[((size_t)bb*SEQ + row1)*D_MODEL + h*HDIM + d] = v;
    }
}

// ---------------------------------------------------------------------------
extern "C" void kernel_launch(void* const* d_in, const int* in_sizes, int n_in,
                              void* d_out, int out_size)
{
    const float* in_q = (const float*)d_in[0];
    const float* in_k = (const float*)d_in[1];
    const float* in_v = (const float*)d_in[2];
    const float* Wq   = (const float*)d_in[3];
    const float* bq   = (const float*)d_in[4];
    const float* Wk   = (const float*)d_in[5];
    const float* bk   = (const float*)d_in[6];
    const float* Wv   = (const float*)d_in[7];
    const float* bv   = (const float*)d_in[8];
    const float* Wo   = (const float*)d_in[9];
    const float* bo   = (const float*)d_in[10];
    float* out = (float*)d_out;

    float *gq, *gk, *gv, *gc, *wq, *wk, *wv, *wo;
    cudaGetSymbolAddress((void**)&gq, g_Q);
    cudaGetSymbolAddress((void**)&gk, g_K);
    cudaGetSymbolAddress((void**)&gv, g_V);
    cudaGetSymbolAddress((void**)&gc, g_C);
    cudaGetSymbolAddress((void**)&wq, g_Wq);
    cudaGetSymbolAddress((void**)&wk, g_Wk);
    cudaGetSymbolAddress((void**)&wv, g_Wv);
    cudaGetSymbolAddress((void**)&wo, g_Wo);

    static int attr_set = 0;
    if (!attr_set) {
        cudaFuncSetAttribute(gemm_qkv,  cudaFuncAttributeMaxDynamicSharedMemorySize, GEMM_SMEM);
        cudaFuncSetAttribute(gemm_oproj, cudaFuncAttributeMaxDynamicSharedMemorySize, GEMM_SMEM);
        cudaFuncSetAttribute(flash_tf32, cudaFuncAttributeMaxDynamicSharedMemorySize, FLASH_SMEM);
        attr_set = 1;
    }

    // Fused weight prepass: 4 matrices, one launch
    const int nW4 = D_MODEL * D_MODEL / 4;   // 256K
    dim3 cvt_grid((nW4 + 255)/256, 1, 4);
    cvt_w_kernel<<<cvt_grid, 256>>>((const float4*)Wq, (float4*)wq,
                                    (const float4*)Wk, (float4*)wk,
                                    (const float4*)Wv, (float4*)wv,
                                    (const float4*)Wo, (float4*)wo, nW4);

    // Fused QKV projections: one launch, grid.z = 3
    dim3 qkv_grid(D_MODEL / 128, MROWS / 128, 3);  // (8, 64, 3)
    gemm_qkv<<<qkv_grid, 256, GEMM_SMEM>>>(in_q, wq, bq, gq,
                                           in_k, wk, bk, gk,
                                           in_v, wv, bv, gv);

    dim3 attn_grid(SEQ / 128, BATCH * NHEADS);     // (16, 64)
    flash_tf32<<<attn_grid, 256, FLASH_SMEM>>>(gq, gk, gv, gc);

    dim3 o_grid(D_MODEL / 128, MROWS / 128);       // (8, 64)
    gemm_oproj<<<o_grid, 256, GEMM_SMEM>>>(gc, wo, bo, out);
}

// round 9
// speedup vs baseline: 5.8556x; 1.4637x over previous
#include <cuda_runtime.h>
#include <cuda_fp16.h>
#include <math.h>
#include <stdint.h>

#define D_MODEL 1024
#define NHEADS  16
#define HDIM    64
#define BATCH   4
#define SEQ     2048
#define MROWS   (BATCH*SEQ)   // 8192

// Scratch (device globals — no allocations allowed). Halves stored as uint16_t.
__device__ uint16_t g_Q[(size_t)MROWS * D_MODEL];   // [B,H,S,hd] half
__device__ uint16_t g_K[(size_t)MROWS * D_MODEL];   // [B,H,S,hd] half
__device__ uint16_t g_V[(size_t)MROWS * D_MODEL];   // [B,H,hd,S] half (pre-transposed!)
__device__ uint16_t g_C[(size_t)MROWS * D_MODEL];   // [B,S,D]    half
// half TRANSPOSED weights: Wt[n][k] = half(W[k][n])
__device__ uint16_t g_Wq[(size_t)D_MODEL * D_MODEL];
__device__ uint16_t g_Wk[(size_t)D_MODEL * D_MODEL];
__device__ uint16_t g_Wv[(size_t)D_MODEL * D_MODEL];
__device__ uint16_t g_Wo[(size_t)D_MODEL * D_MODEL];

__device__ __forceinline__ uint32_t f2h2(float a, float b) {
    __half2 h = __floats2half2_rn(a, b);
    return *reinterpret_cast<uint32_t*>(&h);
}

__device__ __forceinline__ void mma_f16(float c[4], const uint32_t a[4], const uint32_t b[2]) {
    asm volatile(
        "mma.sync.aligned.m16n8k16.row.col.f32.f16.f16.f32 "
        "{%0,%1,%2,%3},{%4,%5,%6,%7},{%8,%9},{%0,%1,%2,%3};"
        : "+f"(c[0]), "+f"(c[1]), "+f"(c[2]), "+f"(c[3])
        : "r"(a[0]), "r"(a[1]), "r"(a[2]), "r"(a[3]), "r"(b[0]), "r"(b[1]));
}

__device__ __forceinline__ void cp_async16(void* sptr, const void* gptr) {
    uint32_t s = (uint32_t)__cvta_generic_to_shared(sptr);
    asm volatile("cp.async.cg.shared.global [%0], [%1], 16;" :: "r"(s), "l"(gptr));
}
__device__ __forceinline__ void cp_commit() { asm volatile("cp.async.commit_group;"); }
template<int N> __device__ __forceinline__ void cp_wait() {
    asm volatile("cp.async.wait_group %0;" :: "n"(N));
}

// ---------------------------------------------------------------------------
// Weight prepass: transpose + half-round all 4 weight matrices.
// Wt[n][k] = half(W[k][n]).  grid (32, 32, 4), block (32, 8).
// ---------------------------------------------------------------------------
__global__ void wtrans_kernel(const float* __restrict__ w0, uint16_t* __restrict__ o0,
                              const float* __restrict__ w1, uint16_t* __restrict__ o1,
                              const float* __restrict__ w2, uint16_t* __restrict__ o2,
                              const float* __restrict__ w3, uint16_t* __restrict__ o3)
{
    __shared__ float tile[32][33];
    const float* W; uint16_t* O;
    switch (blockIdx.z) {
        case 0: W = w0; O = o0; break;
        case 1: W = w1; O = o1; break;
        case 2: W = w2; O = o2; break;
        default: W = w3; O = o3; break;
    }
    int bx = blockIdx.x * 32;   // n block
    int by = blockIdx.y * 32;   // k block
    int tx = threadIdx.x, ty = threadIdx.y;
    #pragma unroll
    for (int i = 0; i < 4; i++)
        tile[ty + 8*i][tx] = W[(size_t)(by + ty + 8*i) * D_MODEL + bx + tx];
    __syncthreads();
    #pragma unroll
    for (int i = 0; i < 4; i++) {
        __half h = __float2half_rn(tile[tx][ty + 8*i]);
        O[(size_t)(bx + ty + 8*i) * D_MODEL + by + tx] = *reinterpret_cast<uint16_t*>(&h);
    }
}

// ===========================================================================
// fp16 tensor-core GEMM: C[M,N] = A[M,K] @ Wt^T + bias  (Wt is half [N][K])
// BM=BN=128, BK=32 halves, 256 threads (8 warps, 64x32 warp tiles), 2-stage.
// CVT_A=1: A raw fp32, LDG->half->STS.  CVT_A=0: A half, cp.async.
// REMAP=1: bias + half-round + head-split store; z==2 (V) stores TRANSPOSED.
// ===========================================================================
#define ALD 40   // halves per smem row (32 + 8 pad); 80 B, 16B-divisible
#define GEMM_SMEM (2 * 128 * ALD * 2 * 2)   // A+B, 2 stages = 40960 B

template<int CVT_A, int REMAP>
__global__ __launch_bounds__(256, 2)
void gemm_h(const void* __restrict__ A0, const uint16_t* __restrict__ W0,
            const float* __restrict__ b0p, void* __restrict__ C0,
            const void* __restrict__ A1, const uint16_t* __restrict__ W1,
            const float* __restrict__ b1p, void* __restrict__ C1,
            const void* __restrict__ A2, const uint16_t* __restrict__ W2,
            const float* __restrict__ b2p, void* __restrict__ C2)
{
    const int K = D_MODEL, N = D_MODEL;
    extern __shared__ uint16_t smh[];
    uint16_t* As = smh;                  // [2][128][ALD]
    uint16_t* Bs = smh + 2 * 128 * ALD;  // [2][128][ALD]

    const void* Av; const uint16_t* Wt; const float* bias; void* Cv;
    const int zsel = blockIdx.z;
    switch (zsel) {
        case 0:  Av = A0; Wt = W0; bias = b0p; Cv = C0; break;
        case 1:  Av = A1; Wt = W1; bias = b1p; Cv = C1; break;
        default: Av = A2; Wt = W2; bias = b2p; Cv = C2; break;
    }
    const float*    Af = (const float*)Av;
    const uint16_t* Ah = (const uint16_t*)Av;

    const int t    = threadIdx.x;
    const int lane = t & 31;
    const int warp = t >> 5;
    const int g    = lane >> 2;
    const int tg   = lane & 3;
    const int wm   = (warp & 1) * 64;
    const int wn   = (warp >> 1) * 32;
    const int m0   = blockIdx.y * 128;
    const int n0   = blockIdx.x * 128;

    const int lrow = t >> 1;            // 0..127
    const int lhlf = (t & 1) * 16;      // half-offset base (16 halves / 16 floats)

    float acc[4][4][4] = {};
    float4 areg[4];

    // ---- Prologue: chunk 0 into slot 0 ----
    if (CVT_A) {
        #pragma unroll
        for (int p = 0; p < 4; p++)
            areg[p] = *(const float4*)&Af[(size_t)(m0 + lrow) * K + lhlf + 4*p];
        #pragma unroll
        for (int p = 0; p < 2; p++) {
            float4 u = areg[2*p], v = areg[2*p + 1];
            uint4 st;
            st.x = f2h2(u.x, u.y); st.y = f2h2(u.z, u.w);
            st.z = f2h2(v.x, v.y); st.w = f2h2(v.z, v.w);
            *(uint4*)&As[lrow * ALD + lhlf + 8*p] = st;
        }
    } else {
        #pragma unroll
        for (int p = 0; p < 2; p++)
            cp_async16(&As[lrow * ALD + lhlf + 8*p],
                       &Ah[(size_t)(m0 + lrow) * K + lhlf + 8*p]);
    }
    #pragma unroll
    for (int p = 0; p < 2; p++)
        cp_async16(&Bs[lrow * ALD + lhlf + 8*p],
                   &Wt[(size_t)(n0 + lrow) * K + lhlf + 8*p]);
    cp_commit();

    const int NCHUNK = K / 32;   // 32
    for (int c = 0; c < NCHUNK; c++) {
        cp_wait<0>();
        __syncthreads();
        const int s = c & 1;
        const bool more = (c + 1 < NCHUNK);
        const int kn = (c + 1) * 32;
        if (more) {
            if (CVT_A) {
                #pragma unroll
                for (int p = 0; p < 4; p++)
                    areg[p] = *(const float4*)&Af[(size_t)(m0 + lrow) * K + kn + lhlf + 4*p];
            } else {
                uint16_t* An = As + (s ^ 1) * 128 * ALD;
                #pragma unroll
                for (int p = 0; p < 2; p++)
                    cp_async16(&An[lrow * ALD + lhlf + 8*p],
                               &Ah[(size_t)(m0 + lrow) * K + kn + lhlf + 8*p]);
            }
            uint16_t* Bn = Bs + (s ^ 1) * 128 * ALD;
            #pragma unroll
            for (int p = 0; p < 2; p++)
                cp_async16(&Bn[lrow * ALD + lhlf + 8*p],
                           &Wt[(size_t)(n0 + lrow) * K + kn + lhlf + 8*p]);
            cp_commit();
        }
        const uint16_t* Ac = As + s * 128 * ALD;
        const uint16_t* Bc = Bs + s * 128 * ALD;
        #pragma unroll
        for (int ks = 0; ks < 2; ks++) {
            const int kk = ks * 16 + 2 * tg;
            uint32_t a[4][4], b[4][2];
            #pragma unroll
            for (int mt = 0; mt < 4; mt++) {
                int m = wm + mt * 16 + g;
                a[mt][0] = *(const uint32_t*)&Ac[m * ALD + kk];
                a[mt][1] = *(const uint32_t*)&Ac[(m + 8) * ALD + kk];
                a[mt][2] = *(const uint32_t*)&Ac[m * ALD + kk + 8];
                a[mt][3] = *(const uint32_t*)&Ac[(m + 8) * ALD + kk + 8];
            }
            #pragma unroll
            for (int nt = 0; nt < 4; nt++) {
                int n = wn + nt * 8 + g;
                b[nt][0] = *(const uint32_t*)&Bc[n * ALD + kk];
                b[nt][1] = *(const uint32_t*)&Bc[n * ALD + kk + 8];
            }
            #pragma unroll
            for (int mt = 0; mt < 4; mt++)
                #pragma unroll
                for (int nt = 0; nt < 4; nt++)
                    mma_f16(acc[mt][nt], a[mt], b[nt]);
        }
        if (more && CVT_A) {
            uint16_t* An = As + (s ^ 1) * 128 * ALD;
            #pragma unroll
            for (int p = 0; p < 2; p++) {
                float4 u = areg[2*p], v = areg[2*p + 1];
                uint4 st;
                st.x = f2h2(u.x, u.y); st.y = f2h2(u.z, u.w);
                st.z = f2h2(v.x, v.y); st.w = f2h2(v.z, v.w);
                *(uint4*)&An[lrow * ALD + lhlf + 8*p] = st;
            }
        }
    }

    // ---- Epilogue ----
    #pragma unroll
    for (int mt = 0; mt < 4; mt++) {
        #pragma unroll
        for (int nt = 0; nt < 4; nt++) {
            int n  = n0 + wn + nt * 8 + 2 * tg;
            float b0v = bias[n], b1v = bias[n + 1];
            #pragma unroll
            for (int half = 0; half < 2; half++) {
                int m = m0 + wm + mt * 16 + g + half * 8;
                float vx = acc[mt][nt][half*2 + 0] + b0v;
                float vy = acc[mt][nt][half*2 + 1] + b1v;
                if (REMAP) {
                    uint16_t* Ch = (uint16_t*)Cv;
                    int bb = m >> 11, srow = m & 2047;
                    int hh = n >> 6, dd = n & 63;
                    if (zsel == 2) {
                        // V: store transposed [B,H,hd,S]
                        __half h0 = __float2half_rn(vx), h1 = __float2half_rn(vy);
                        size_t base = ((size_t)(bb * NHEADS + hh)) * HDIM;
                        Ch[(base + dd)     * SEQ + srow] = *reinterpret_cast<uint16_t*>(&h0);
                        Ch[(base + dd + 1) * SEQ + srow] = *reinterpret_cast<uint16_t*>(&h1);
                    } else {
                        *(uint32_t*)&Ch[(((size_t)(bb * NHEADS + hh)) * SEQ + srow) * HDIM + dd]
                            = f2h2(vx, vy);
                    }
                } else {
                    float* Cf = (float*)Cv;
                    *(float2*)&Cf[(size_t)m * N + n] = make_float2(vx, vy);
                }
            }
        }
    }
}

// ---------------------------------------------------------------------------
// Causal flash attention, fp16 mma, register-resident softmax.
// Q/K half [B,H,S,hd]; V half PRE-TRANSPOSED [B,H,hd,S]; ctx half [B,S,D].
// CTA = 256 threads (8 warps) on 128q x 64k tile; warp = 16q x 64k.
// ---------------------------------------------------------------------------
#define FLD 72   // halves per smem row (64 + 8 pad); 144 B, 16B-divisible
#define FLASH_SMEM ((128*FLD + 128*FLD + 2*64*FLD + 2*64*FLD) * 2)   // 73728 B

__global__ __launch_bounds__(256, 2)
void flash_h(const uint16_t* __restrict__ Q, const uint16_t* __restrict__ K,
             const uint16_t* __restrict__ V, uint16_t* __restrict__ ctx)
{
    extern __shared__ uint16_t smh[];
    uint16_t* Qs = smh;                    // [128][FLD]
    uint16_t* Ps = smh + 128 * FLD;        // [128][FLD]
    uint16_t* Ks = smh + 2 * 128 * FLD;    // [2][64][FLD]   Ks[k][d]
    uint16_t* Vs = Ks + 2 * 64 * FLD;      // [2][64][FLD]   Vs[d][k]

    const int t    = threadIdx.x;
    const int lane = t & 31;
    const int warp = t >> 5;
    const int g    = lane >> 2;
    const int tg   = lane & 3;
    const int wq   = warp * 16;
    const int qt   = blockIdx.x;
    const int bh   = blockIdx.y;
    const int q0   = qt * 128;
    const int kt_max = 2 * qt + 1;
    const float scl = 0.125f;

    // cooperative load indices
    const int qr = t >> 1, qc = (t & 1) * 32;        // Q: 128 rows, 2 thr/row
    const int kr = t >> 2, kc = (t & 3) * 16;        // K/V: 64 rows, 4 thr/row

    {
        const uint16_t* Qb = Q + ((size_t)bh * SEQ + q0) * HDIM;
        #pragma unroll
        for (int p = 0; p < 4; p++)
            cp_async16(&Qs[qr * FLD + qc + 8*p], &Qb[qr * HDIM + qc + 8*p]);
    }
    {
        const uint16_t* Kb = K + (size_t)bh * SEQ * HDIM;
        const uint16_t* Vb = V + (size_t)bh * HDIM * SEQ;
        #pragma unroll
        for (int p = 0; p < 2; p++) {
            cp_async16(&Ks[kr * FLD + kc + 8*p], &Kb[kr * HDIM + kc + 8*p]);
            cp_async16(&Vs[kr * FLD + kc + 8*p], &Vb[(size_t)kr * SEQ + kc + 8*p]);
        }
    }
    cp_commit();

    float m0r = -INFINITY, m1r = -INFINITY;
    float l0r = 0.f, l1r = 0.f;
    float o[8][4] = {};

    const int row0 = q0 + wq + g;
    const int row1 = row0 + 8;

    for (int kt = 0; kt <= kt_max; kt++) {
        cp_wait<0>();
        __syncthreads();
        const int s = kt & 1;
        if (kt < kt_max) {
            const int kn = (kt + 1) * 64;
            const uint16_t* Kb = K + ((size_t)bh * SEQ + kn) * HDIM;
            const uint16_t* Vb = V + (size_t)bh * HDIM * SEQ + kn;
            uint16_t* Kn = Ks + (s ^ 1) * 64 * FLD;
            uint16_t* Vn = Vs + (s ^ 1) * 64 * FLD;
            #pragma unroll
            for (int p = 0; p < 2; p++) {
                cp_async16(&Kn[kr * FLD + kc + 8*p], &Kb[kr * HDIM + kc + 8*p]);
                cp_async16(&Vn[kr * FLD + kc + 8*p], &Vb[(size_t)kr * SEQ + kc + 8*p]);
            }
            cp_commit();
        }
        const uint16_t* Kc = Ks + s * 64 * FLD;
        const uint16_t* Vc = Vs + s * 64 * FLD;
        const int k0 = kt * 64;

        // ---- S = Q K^T ----
        float sc[8][4] = {};
        #pragma unroll
        for (int ks = 0; ks < 4; ks++) {
            const int kk = ks * 16 + 2 * tg;
            uint32_t a[4], b[8][2];
            a[0] = *(const uint32_t*)&Qs[(wq + g) * FLD + kk];
            a[1] = *(const uint32_t*)&Qs[(wq + g + 8) * FLD + kk];
            a[2] = *(const uint32_t*)&Qs[(wq + g) * FLD + kk + 8];
            a[3] = *(const uint32_t*)&Qs[(wq + g + 8) * FLD + kk + 8];
            #pragma unroll
            for (int nt = 0; nt < 8; nt++) {
                int n = nt * 8 + g;
                b[nt][0] = *(const uint32_t*)&Kc[n * FLD + kk];
                b[nt][1] = *(const uint32_t*)&Kc[n * FLD + kk + 8];
            }
            #pragma unroll
            for (int nt = 0; nt < 8; nt++)
                mma_f16(sc[nt], a, b[nt]);
        }

        // ---- scale + causal mask ----
        if (k0 + 63 > row0) {
            #pragma unroll
            for (int nt = 0; nt < 8; nt++) {
                int c = k0 + nt * 8 + 2 * tg;
                sc[nt][0] = (c     > row0) ? -INFINITY : sc[nt][0] * scl;
                sc[nt][1] = (c + 1 > row0) ? -INFINITY : sc[nt][1] * scl;
                sc[nt][2] = (c     > row1) ? -INFINITY : sc[nt][2] * scl;
                sc[nt][3] = (c + 1 > row1) ? -INFINITY : sc[nt][3] * scl;
            }
        } else {
            #pragma unroll
            for (int nt = 0; nt < 8; nt++)
                #pragma unroll
                for (int i = 0; i < 4; i++) sc[nt][i] *= scl;
        }

        // ---- row max (registers + quad shuffle) ----
        float mx0 = -INFINITY, mx1 = -INFINITY;
        #pragma unroll
        for (int nt = 0; nt < 8; nt++) {
            mx0 = fmaxf(mx0, fmaxf(sc[nt][0], sc[nt][1]));
            mx1 = fmaxf(mx1, fmaxf(sc[nt][2], sc[nt][3]));
        }
        mx0 = fmaxf(mx0, __shfl_xor_sync(0xffffffff, mx0, 1));
        mx0 = fmaxf(mx0, __shfl_xor_sync(0xffffffff, mx0, 2));
        mx1 = fmaxf(mx1, __shfl_xor_sync(0xffffffff, mx1, 1));
        mx1 = fmaxf(mx1, __shfl_xor_sync(0xffffffff, mx1, 2));

        float mn0 = fmaxf(m0r, mx0), mn1 = fmaxf(m1r, mx1);
        float al0 = __expf(m0r - mn0), al1 = __expf(m1r - mn1);
        m0r = mn0; m1r = mn1;

        // ---- exp (half-rounded), row sums over rounded values, write P ----
        float s0 = 0.f, s1 = 0.f;
        #pragma unroll
        for (int nt = 0; nt < 8; nt++) {
            __half2 hp0 = __floats2half2_rn(__expf(sc[nt][0] - mn0), __expf(sc[nt][1] - mn0));
            __half2 hp1 = __floats2half2_rn(__expf(sc[nt][2] - mn1), __expf(sc[nt][3] - mn1));
            float2 r0 = __half22float2(hp0);
            float2 r1 = __half22float2(hp1);
            s0 += r0.x + r0.y;
            s1 += r1.x + r1.y;
            int c = nt * 8 + 2 * tg;
            *(uint32_t*)&Ps[(wq + g) * FLD + c]     = *reinterpret_cast<uint32_t*>(&hp0);
            *(uint32_t*)&Ps[(wq + g + 8) * FLD + c] = *reinterpret_cast<uint32_t*>(&hp1);
        }
        s0 += __shfl_xor_sync(0xffffffff, s0, 1);
        s0 += __shfl_xor_sync(0xffffffff, s0, 2);
        s1 += __shfl_xor_sync(0xffffffff, s1, 1);
        s1 += __shfl_xor_sync(0xffffffff, s1, 2);
        l0r = l0r * al0 + s0;
        l1r = l1r * al1 + s1;
        #pragma unroll
        for (int nt = 0; nt < 8; nt++) {
            o[nt][0] *= al0; o[nt][1] *= al0;
            o[nt][2] *= al1; o[nt][3] *= al1;
        }
        __syncwarp();   // P tile is warp-private

        // ---- O += P V ----
        #pragma unroll
        for (int ks = 0; ks < 4; ks++) {
            const int kk = ks * 16 + 2 * tg;
            uint32_t a[4], b[8][2];
            a[0] = *(const uint32_t*)&Ps[(wq + g) * FLD + kk];
            a[1] = *(const uint32_t*)&Ps[(wq + g + 8) * FLD + kk];
            a[2] = *(const uint32_t*)&Ps[(wq + g) * FLD + kk + 8];
            a[3] = *(const uint32_t*)&Ps[(wq + g + 8) * FLD + kk + 8];
            #pragma unroll
            for (int nt = 0; nt < 8; nt++) {
                int d = nt * 8 + g;
                b[nt][0] = *(const uint32_t*)&Vc[d * FLD + kk];
                b[nt][1] = *(const uint32_t*)&Vc[d * FLD + kk + 8];
            }
            #pragma unroll
            for (int nt = 0; nt < 8; nt++)
                mma_f16(o[nt], a, b[nt]);
        }
    }

    // Epilogue: normalize, half-round, write ctx [B,S,D] half
    const int bb = bh >> 4;
    const int hh = bh & 15;
    const float il0 = 1.f / l0r, il1 = 1.f / l1r;
    #pragma unroll
    for (int nt = 0; nt < 8; nt++) {
        int d = nt * 8 + 2 * tg;
        *(uint32_t*)&ctx[((size_t)bb * SEQ + row0) * D_MODEL + hh * HDIM + d]
            = f2h2(o[nt][0] * il0, o[nt][1] * il0);
        *(uint32_t*)&ctx[((size_t)bb * SEQ + row1) * D_MODEL + hh * HDIM + d]
            = f2h2(o[nt][2] * il1, o[nt][3] * il1);
    }
}

// ---------------------------------------------------------------------------
extern "C" void kernel_launch(void* const* d_in, const int* in_sizes, int n_in,
                              void* d_out, int out_size)
{
    const float* in_q = (const float*)d_in[0];
    const float* in_k = (const float*)d_in[1];
    const float* in_v = (const float*)d_in[2];
    const float* Wq   = (const float*)d_in[3];
    const float* bq   = (const float*)d_in[4];
    const float* Wk   = (const float*)d_in[5];
    const float* bk   = (const float*)d_in[6];
    const float* Wv   = (const float*)d_in[7];
    const float* bv   = (const float*)d_in[8];
    const float* Wo   = (const float*)d_in[9];
    const float* bo   = (const float*)d_in[10];
    float* out = (float*)d_out;

    uint16_t *gq, *gk, *gv, *gc, *wq, *wk, *wv, *wo;
    cudaGetSymbolAddress((void**)&gq, g_Q);
    cudaGetSymbolAddress((void**)&gk, g_K);
    cudaGetSymbolAddress((void**)&gv, g_V);
    cudaGetSymbolAddress((void**)&gc, g_C);
    cudaGetSymbolAddress((void**)&wq, g_Wq);
    cudaGetSymbolAddress((void**)&wk, g_Wk);
    cudaGetSymbolAddress((void**)&wv, g_Wv);
    cudaGetSymbolAddress((void**)&wo, g_Wo);

    static int attr_set = 0;
    if (!attr_set) {
        cudaFuncSetAttribute(gemm_h<1,1>, cudaFuncAttributeMaxDynamicSharedMemorySize, GEMM_SMEM);
        cudaFuncSetAttribute(gemm_h<0,0>, cudaFuncAttributeMaxDynamicSharedMemorySize, GEMM_SMEM);
        cudaFuncSetAttribute(flash_h,     cudaFuncAttributeMaxDynamicSharedMemorySize, FLASH_SMEM);
        attr_set = 1;
    }

    // Weight prepass: transpose + half-round, one launch
    dim3 wt_grid(32, 32, 4);
    wtrans_kernel<<<wt_grid, dim3(32, 8)>>>(Wq, wq, Wk, wk, Wv, wv, Wo, wo);

    // Fused QKV projections, one launch (z selects problem)
    dim3 qkv_grid(D_MODEL / 128, MROWS / 128, 3);   // (8, 64, 3)
    gemm_h<1,1><<<qkv_grid, 256, GEMM_SMEM>>>(in_q, wq, bq, gq,
                                              in_k, wk, bk, gk,
                                              in_v, wv, bv, gv);

    dim3 attn_grid(SEQ / 128, BATCH * NHEADS);      // (16, 64)
    flash_h<<<attn_grid, 256, FLASH_SMEM>>>(gq, gk, gv, gc);

    // O-projection: A = half ctx, output fp32 + bias
    dim3 o_grid(D_MODEL / 128, MROWS / 128, 1);     // (8, 64)
    gemm_h<0,0><<<o_grid, 256, GEMM_SMEM>>>(gc, wo, bo, out,
                                            gc, wo, bo, out,
                                            gc, wo, bo, out);
}